// round 8
// baseline (speedup 1.0000x reference)
#include <cuda_runtime.h>
#include <math.h>

#define BATCH 32
#define H 1024
#define W 1024
#define WR 513
#define NPIX (WR * H)
#define TP 56
#define TWO_PI 6.28318530717958647692f

#define PADI(e) ((e) + 5 * ((e) >> 5))
#define FFT_SM 1184

__device__ float2 g_bufA[(size_t)BATCH * H * WR];   /* row-fft out [b][r][c]; later pu [b][c][r] floats */
__device__ float2 g_bufB[(size_t)BATCH * WR * H];   /* transposed [b][c][r] */
__device__ float2 g_tw[1024];
__device__ float  g_coeff[BATCH * TP];
__device__ double g_stats[BATCH * 4];   /* sgx, sgy, sgx2, sgy2 */
__device__ int    g_magmax[BATCH];
__device__ int    g_maskcnt;

__global__ void init_kernel() {
    int t = threadIdx.x;   /* 1024 threads */
    float s, c;
    sincospif(-(float)t / 512.0f, &s, &c);
    g_tw[t] = make_float2(c, s);
    for (int i = t; i < BATCH * TP; i += 1024) g_coeff[i] = 0.0f;
    if (t < BATCH * 4) g_stats[t] = 0.0;
    if (t < BATCH)     g_magmax[t] = 0;
    if (t == 0)        g_maskcnt = 0;
}

/* DFT-16 fully in registers. */
__device__ __forceinline__ void dft16(float* vr, float* vi) {
    const float C1 = 0.92387953251128675613f;
    const float S1 = 0.38268343236508977173f;
    const float C2 = 0.70710678118654752440f;
    float tr[4][4], ti[4][4];
#pragma unroll
    for (int a = 0; a < 4; ++a) {
        float x0r = vr[a],      x0i = vi[a];
        float x1r = vr[a + 4],  x1i = vi[a + 4];
        float x2r = vr[a + 8],  x2i = vi[a + 8];
        float x3r = vr[a + 12], x3i = vi[a + 12];
        float s0r = x0r + x2r, s0i = x0i + x2i;
        float d0r = x0r - x2r, d0i = x0i - x2i;
        float s1r = x1r + x3r, s1i = x1i + x3i;
        float d1r = x1r - x3r, d1i = x1i - x3i;
        tr[a][0] = s0r + s1r; ti[a][0] = s0i + s1i;
        tr[a][1] = d0r + d1i; ti[a][1] = d0i - d1r;
        tr[a][2] = s0r - s1r; ti[a][2] = s0i - s1i;
        tr[a][3] = d0r - d1i; ti[a][3] = d0i + d1r;
    }
#pragma unroll
    for (int a = 1; a < 4; ++a) {
#pragma unroll
        for (int c = 1; c < 4; ++c) {
            int k = a * c;
            float wr, wi;
            if (k == 1)      { wr =  C1; wi = -S1; }
            else if (k == 2) { wr =  C2; wi = -C2; }
            else if (k == 3) { wr =  S1; wi = -C1; }
            else if (k == 4) { wr = 0.f; wi = -1.f; }
            else if (k == 6) { wr = -C2; wi = -C2; }
            else             { wr = -C1; wi =  S1; }
            float r = tr[a][c] * wr - ti[a][c] * wi;
            ti[a][c] = tr[a][c] * wi + ti[a][c] * wr;
            tr[a][c] = r;
        }
    }
#pragma unroll
    for (int c = 0; c < 4; ++c) {
        float s0r = tr[0][c] + tr[2][c], s0i = ti[0][c] + ti[2][c];
        float d0r = tr[0][c] - tr[2][c], d0i = ti[0][c] - ti[2][c];
        float s1r = tr[1][c] + tr[3][c], s1i = ti[1][c] + ti[3][c];
        float d1r = tr[1][c] - tr[3][c], d1i = ti[1][c] - ti[3][c];
        vr[c]      = s0r + s1r; vi[c]      = s0i + s1i;
        vr[c + 4]  = d0r + d1i; vi[c + 4]  = d0i - d1r;
        vr[c + 8]  = s0r - s1r; vi[c + 8]  = s0i - s1i;
        vr[c + 12] = d0r - d1i; vi[c + 12] = d0i + d1r;
    }
}

__device__ __forceinline__ void fft_stages01(float* vr, float* vi,
                                             float* SR, float* SI, int t) {
    dft16(vr, vi);
#pragma unroll
    for (int k = 0; k < 16; ++k) {
        int e = PADI(16 * t + k);
        SR[e] = vr[k]; SI[e] = vi[k];
    }
    __syncthreads();
#pragma unroll
    for (int m = 0; m < 16; ++m) {
        int e = PADI(t + 64 * m);
        vr[m] = SR[e]; vi[m] = SI[e];
    }
    int jm = t & 15;
#pragma unroll
    for (int m = 1; m < 16; ++m) {
        float2 w = g_tw[4 * m * jm];
        float r = vr[m] * w.x - vi[m] * w.y;
        vi[m] = vr[m] * w.y + vi[m] * w.x;
        vr[m] = r;
    }
    dft16(vr, vi);
    __syncthreads();
    int base1 = (t >> 4) * 256 + jm;
#pragma unroll
    for (int k = 0; k < 16; ++k) {
        int e = PADI(base1 + 16 * k);
        SR[e] = vr[k]; SI[e] = vi[k];
    }
    __syncthreads();
}

__device__ __forceinline__ void fft_stage2(const float* SR, const float* SI,
                                           int j, float* yr, float* yi) {
    float ar[4], ai[4];
#pragma unroll
    for (int m = 0; m < 4; ++m) {
        int e = PADI(j + 256 * m);
        ar[m] = SR[e]; ai[m] = SI[e];
    }
#pragma unroll
    for (int m = 1; m < 4; ++m) {
        float2 w = g_tw[m * j];
        float r = ar[m] * w.x - ai[m] * w.y;
        ai[m] = ar[m] * w.y + ai[m] * w.x;
        ar[m] = r;
    }
    float s0r = ar[0] + ar[2], s0i = ai[0] + ai[2];
    float d0r = ar[0] - ar[2], d0i = ai[0] - ai[2];
    float s1r = ar[1] + ar[3], s1i = ai[1] + ai[3];
    float d1r = ar[1] - ar[3], d1i = ai[1] - ai[3];
    yr[0] = s0r + s1r; yi[0] = s0i + s1i;
    yr[1] = d0r + d1i; yi[1] = d0i - d1r;
    yr[2] = s0r - s1r; yi[2] = s0i - s1i;
    yr[3] = d0r - d1i; yi[3] = d0i + d1r;
}

/* Two real rows packed per FFT; 2 FFTs per block; row-major coalesced output. */
__global__ void __launch_bounds__(128) row_fft_kernel(const float* __restrict__ x) {
    __shared__ float smr[2][FFT_SM], smi[2][FFT_SM];
    int f = threadIdx.x >> 6;
    int t = threadIdx.x & 63;
    int pr = blockIdx.x * 2 + f;
    float* SR = smr[f]; float* SI = smi[f];
    const float* rowA = x + (size_t)(2 * pr) * W;
    const float* rowB = rowA + W;
    float vr[16], vi[16];
#pragma unroll
    for (int m = 0; m < 16; ++m) {
        int idx = t + 64 * m;
        vr[m] = rowA[idx]; vi[m] = rowB[idx];
    }
    fft_stages01(vr, vi, SR, SI, t);
#pragma unroll
    for (int u = 0; u < 4; ++u) {
        int j = t + 64 * u;
        float yr[4], yi[4];
        fft_stage2(SR, SI, j, yr, yi);
#pragma unroll
        for (int k = 0; k < 4; ++k) {
            int e = PADI(j + 256 * k);
            SR[e] = yr[k]; SI[e] = yi[k];
        }
    }
    __syncthreads();
    float2* outA = g_bufA + (size_t)(2 * pr) * WR;
    float2* outB = outA + WR;
    for (int c = t; c < WR; c += 64) {
        int cn = (1024 - c) & 1023;
        float Zcr = SR[PADI(c)],  Zci = SI[PADI(c)];
        float Znr = SR[PADI(cn)], Zni = SI[PADI(cn)];
        float ar = 0.5f * (Zcr + Znr);
        float ai = 0.5f * (Zci - Zni);
        float dr = Zcr - Znr;
        float di = Zci + Zni;
        outA[c] = make_float2(ar, ai);
        outB[c] = make_float2(0.5f * di, -0.5f * dr);
    }
}

__global__ void transpose_kernel() {
    __shared__ float2 tile[32][33];
    int b  = blockIdx.z;
    int c0 = blockIdx.x * 32;
    int r0 = blockIdx.y * 32;
    int tx = threadIdx.x, ty = threadIdx.y;
    const float2* A = g_bufA + (size_t)b * H * WR;
    float2*       B = g_bufB + (size_t)b * WR * H;
#pragma unroll
    for (int i = ty; i < 32; i += 8) {
        int r = r0 + i, c = c0 + tx;
        if (c < WR) tile[i][tx] = A[(size_t)r * WR + c];
    }
    __syncthreads();
#pragma unroll
    for (int i = ty; i < 32; i += 8) {
        int c = c0 + i, r = r0 + tx;
        if (c < WR) B[(size_t)c * H + r] = tile[tx][i];
    }
}

/* 2 FFTs per block; epilogue: pu write, magnitude max, fused grad-y stats. */
__global__ void __launch_bounds__(128) col_fft_kernel() {
    __shared__ float smr[2][FFT_SM], smi[2][FFT_SM];
    __shared__ float sred[4], sgy[4], sgy2[4];
    int f = threadIdx.x >> 6;
    int t = threadIdx.x & 63;
    int blk = blockIdx.x * 2 + f;          /* b*WR + c */
    float* SR = smr[f]; float* SI = smi[f];
    const float2* in = g_bufB + (size_t)blk * H;
    float vr[16], vi[16];
#pragma unroll
    for (int m = 0; m < 16; ++m) {
        float2 z = in[t + 64 * m];
        vr[m] = z.x; vi[m] = z.y;
    }
    fft_stages01(vr, vi, SR, SI, t);

    float* pu = (float*)g_bufA;
    size_t outb = (size_t)blk * H;
    float maxm2 = 0.0f;
    float phv[16];
#pragma unroll
    for (int u = 0; u < 4; ++u) {
        int j = t + 64 * u;
        float yr[4], yi[4];
        fft_stage2(SR, SI, j, yr, yi);
#pragma unroll
        for (int k = 0; k < 4; ++k) {
            float m2 = fmaf(yr[k], yr[k], yi[k] * yi[k]);
            maxm2 = fmaxf(maxm2, m2);
            float ph = atan2f(yi[k], yr[k]);
            if (ph < 0.0f) ph += TWO_PI;
            phv[u + 4 * k] = ph;
            SR[PADI(j + 256 * k)] = ph;   /* in-place: thread-private slot set */
            pu[outb + j + 256 * k] = ph;
        }
    }
    __syncthreads();

    /* grad-y (along r) stats from smem phase column */
    float sy = 0.0f, sy2 = 0.0f;
#pragma unroll
    for (int s = 0; s < 16; ++s) {
        int r = t + 64 * s;
        float pc = phv[s];
        float gy;
        if (r == 0)          gy = SR[PADI(1)] - pc;
        else if (r == 1023)  gy = pc - SR[PADI(1022)];
        else                 gy = 0.5f * (SR[PADI(r + 1)] - SR[PADI(r - 1)]);
        sy += gy;
        sy2 = fmaf(gy, gy, sy2);
    }
#pragma unroll
    for (int o = 16; o; o >>= 1) {
        maxm2 = fmaxf(maxm2, __shfl_xor_sync(0xffffffffu, maxm2, o));
        sy  += __shfl_xor_sync(0xffffffffu, sy,  o);
        sy2 += __shfl_xor_sync(0xffffffffu, sy2, o);
    }
    int w = threadIdx.x >> 5;
    if ((threadIdx.x & 31) == 0) { sred[w] = maxm2; sgy[w] = sy; sgy2[w] = sy2; }
    __syncthreads();
    if (t == 0) {
        int b = blk / WR;
        float mm = fmaxf(sred[2 * f], sred[2 * f + 1]);
        atomicMax(&g_magmax[b], __float_as_int(sqrtf(mm)));
        atomicAdd(&g_stats[b * 4 + 1], (double)(sgy[2 * f] + sgy[2 * f + 1]));
        atomicAdd(&g_stats[b * 4 + 3], (double)(sgy2[2 * f] + sgy2[2 * f + 1]));
    }
}

/* grad-x only stats (gy fused into col_fft) */
__global__ void __launch_bounds__(256) statsx_kernel() {
    int b = blockIdx.y;
    const float4* pu4 = (const float4*)((const float*)g_bufA + (size_t)b * NPIX);
    float sx = 0.0f, sx2 = 0.0f;
    const int NQ = NPIX / 4;
    for (int q = blockIdx.x * 256 + threadIdx.x; q < NQ; q += gridDim.x * 256) {
        int c = q >> 8;
        float4 up, dn; float fac;
        if (c == 0)          { dn = pu4[q + 256]; up = pu4[q];       fac = 1.0f; }
        else if (c == WR - 1){ up = pu4[q - 256]; dn = pu4[q];       fac = 1.0f; }
        else                 { up = pu4[q - 256]; dn = pu4[q + 256]; fac = 0.5f; }
        float g0 = fac * (dn.x - up.x);
        float g1 = fac * (dn.y - up.y);
        float g2 = fac * (dn.z - up.z);
        float g3 = fac * (dn.w - up.w);
        sx += g0 + g1 + g2 + g3;
        sx2 = fmaf(g0, g0, fmaf(g1, g1, fmaf(g2, g2, fmaf(g3, g3, sx2))));
    }
    __shared__ double sbuf[8];
    double v2[2] = {(double)sx, (double)sx2};
#pragma unroll
    for (int qq = 0; qq < 2; ++qq) {
        double tt = v2[qq];
#pragma unroll
        for (int o = 16; o; o >>= 1) tt += __shfl_down_sync(0xffffffffu, tt, o);
        if ((threadIdx.x & 31) == 0) sbuf[threadIdx.x >> 5] = tt;
        __syncthreads();
        if (threadIdx.x < 8) {
            tt = sbuf[threadIdx.x];
#pragma unroll
            for (int o = 4; o; o >>= 1) tt += __shfl_down_sync(0xffu, tt, o);
            if (threadIdx.x == 0) atomicAdd(&g_stats[b * 4 + 2 * qq], tt);
        }
        __syncthreads();
    }
}

/* coeffs GEMM: split-K (two 64-thread halves), 4x7 register blocking */
#define KC 64
__global__ void __launch_bounds__(128) gemm_kernel() {
    __shared__ float pm_s[BATCH][KC + 4];
    __shared__ float z_s[TP][KC + 4];
    const float* pu = (const float*)g_bufA;
    int tid = threadIdx.x;
    int kh = tid >> 6;
    int h  = tid & 63;
    int b0 = (h >> 3) * 4;
    int t0 = (h & 7) * 7;
    const int kb = kh * 32;
    float acc[4][7];
#pragma unroll
    for (int a = 0; a < 4; ++a)
#pragma unroll
        for (int j = 0; j < 7; ++j) acc[a][j] = 0.0f;

    for (int k0 = blockIdx.x * KC; k0 < NPIX; k0 += gridDim.x * KC) {
        __syncthreads();
        if (tid < 64) {
            int pix = k0 + tid;
            int c = pix >> 10;
            int r = pix & 1023;
            float xg = (float)c * (1.0f / 256.0f) - 1.0f;
            float yg = (float)r * (2.0f / 1023.0f) - 1.0f;
            float rr = xg * xg + yg * yg;
            float rho = sqrtf(rr);
            float mk = (rho <= 1.0f) ? 1.0f : 0.0f;
            float inv = 1.0f / rho;
            float c1 = xg * inv, s1 = yg * inv;
            float q1 = rho, q2 = q1 * q1;
            float q3 = q2 * q1, q4 = q2 * q2, q5 = q3 * q2, q6 = q3 * q3;
            float q7 = q4 * q3, q8 = q4 * q4, q9 = q5 * q4;
            float c2 = c1 * c1 - s1 * s1, s2 = 2.0f * s1 * c1;
            float c3 = c1 * c2 - s1 * s2, s3 = s1 * c2 + c1 * s2;
            float c4 = c1 * c3 - s1 * s3, s4 = s1 * c3 + c1 * s3;
            float c5 = c1 * c4 - s1 * s4, s5 = s1 * c4 + c1 * s4;
            float c6 = c1 * c5 - s1 * s5, s6 = s1 * c5 + c1 * s5;
            float c7 = c1 * c6 - s1 * s6, s7 = s1 * c6 + c1 * s6;
            float c8 = c1 * c7 - s1 * s7, s8 = s1 * c7 + c1 * s7;
            float c9 = c1 * c8 - s1 * s8, s9 = s1 * c8 + c1 * s8;
#define ZST(tt, val) z_s[tt][tid] = (val) * mk
            ZST(0, 1.0f);
            ZST(1, q1 * s1);
            ZST(2, q1 * c1);
            ZST(3, q2 * s2);
            ZST(4, 2.0f * q2 - 1.0f);
            ZST(5, q2 * c2);
            ZST(6, q3 * s3);
            float R31 = 3.0f * q3 - 2.0f * q1;
            ZST(7, R31 * s1);
            ZST(8, R31 * c1);
            ZST(9, q3 * c3);
            ZST(10, q4 * s4);
            float R42 = 4.0f * q4 - 3.0f * q2;
            ZST(11, R42 * s2);
            ZST(12, 6.0f * q4 - 6.0f * q2 + 1.0f);
            ZST(13, R42 * c2);
            ZST(14, q4 * c4);
            ZST(15, q5 * s5);
            float R53 = 5.0f * q5 - 4.0f * q3;
            ZST(16, R53 * s3);
            float R51 = 10.0f * q5 - 12.0f * q3 + 3.0f * q1;
            ZST(17, R51 * s1);
            ZST(18, R51 * c1);
            ZST(19, R53 * c3);
            ZST(20, q5 * c5);
            ZST(21, q6 * s6);
            float R64 = 6.0f * q6 - 5.0f * q4;
            ZST(22, R64 * s4);
            float R62 = 15.0f * q6 - 20.0f * q4 + 6.0f * q2;
            ZST(23, R62 * s2);
            ZST(24, 20.0f * q6 - 30.0f * q4 + 12.0f * q2 - 1.0f);
            ZST(25, R62 * c2);
            ZST(26, R64 * c4);
            ZST(27, q6 * c6);
            ZST(28, q7 * s7);
            float R75 = 7.0f * q7 - 6.0f * q5;
            ZST(29, R75 * s5);
            float R73 = 21.0f * q7 - 30.0f * q5 + 10.0f * q3;
            ZST(30, R73 * s3);
            float R71 = 35.0f * q7 - 60.0f * q5 + 30.0f * q3 - 4.0f * q1;
            ZST(31, R71 * s1);
            ZST(32, R71 * c1);
            ZST(33, R73 * c3);
            ZST(34, R75 * c5);
            ZST(35, q7 * c7);
            ZST(36, q8 * s8);
            float R86 = 8.0f * q8 - 7.0f * q6;
            ZST(37, R86 * s6);
            float R84 = 28.0f * q8 - 42.0f * q6 + 15.0f * q4;
            ZST(38, R84 * s4);
            float R82 = 56.0f * q8 - 105.0f * q6 + 60.0f * q4 - 10.0f * q2;
            ZST(39, R82 * s2);
            ZST(40, 70.0f * q8 - 140.0f * q6 + 90.0f * q4 - 20.0f * q2 + 1.0f);
            ZST(41, R82 * c2);
            ZST(42, R84 * c4);
            ZST(43, R86 * c6);
            ZST(44, q8 * c8);
            ZST(45, q9 * s9);
            float R97 = 9.0f * q9 - 8.0f * q7;
            ZST(46, R97 * s7);
            float R95 = 36.0f * q9 - 56.0f * q7 + 21.0f * q5;
            ZST(47, R95 * s5);
            float R93 = 84.0f * q9 - 168.0f * q7 + 105.0f * q5 - 20.0f * q3;
            ZST(48, R93 * s3);
            float R91 = 126.0f * q9 - 280.0f * q7 + 210.0f * q5 - 60.0f * q3 + 5.0f * q1;
            ZST(49, R91 * s1);
            ZST(50, R91 * c1);
            ZST(51, R93 * c3);
            ZST(52, R95 * c5);
            ZST(53, R97 * c7);
            ZST(54, q9 * c9);
            z_s[55][tid] = 0.0f;
#undef ZST
            unsigned bal = __ballot_sync(0xffffffffu, mk > 0.5f);
            if ((tid & 31) == 0) atomicAdd(&g_maskcnt, __popc(bal));
        } else {
            int t = tid - 64;
#pragma unroll
            for (int row = 0; row < BATCH; ++row)
                pm_s[row][t] = pu[(size_t)row * NPIX + k0 + t];
        }
        __syncthreads();
#pragma unroll
        for (int kk = 0; kk < 32; kk += 4) {
            float4 a0 = *(const float4*)&pm_s[b0][kb + kk];
            float4 a1 = *(const float4*)&pm_s[b0 + 1][kb + kk];
            float4 a2 = *(const float4*)&pm_s[b0 + 2][kb + kk];
            float4 a3 = *(const float4*)&pm_s[b0 + 3][kb + kk];
#pragma unroll
            for (int j = 0; j < 7; ++j) {
                float4 zz = *(const float4*)&z_s[t0 + j][kb + kk];
                acc[0][j] = fmaf(a0.x, zz.x, fmaf(a0.y, zz.y, fmaf(a0.z, zz.z, fmaf(a0.w, zz.w, acc[0][j]))));
                acc[1][j] = fmaf(a1.x, zz.x, fmaf(a1.y, zz.y, fmaf(a1.z, zz.z, fmaf(a1.w, zz.w, acc[1][j]))));
                acc[2][j] = fmaf(a2.x, zz.x, fmaf(a2.y, zz.y, fmaf(a2.z, zz.z, fmaf(a2.w, zz.w, acc[2][j]))));
                acc[3][j] = fmaf(a3.x, zz.x, fmaf(a3.y, zz.y, fmaf(a3.z, zz.z, fmaf(a3.w, zz.w, acc[3][j]))));
            }
        }
    }
#pragma unroll
    for (int a = 0; a < 4; ++a)
#pragma unroll
        for (int j = 0; j < 7; ++j)
            atomicAdd(&g_coeff[(b0 + a) * TP + t0 + j], acc[a][j]);
}

__global__ void finalize_kernel(float* __restrict__ out) {
    int b = blockIdx.x;
    int j = threadIdx.x;
    if (j < 55) {
        out[b * 60 + j] = g_coeff[b * TP + j] / (float)g_maskcnt;
    } else if (j < 60) {
        double N = (double)NPIX;
        double sx = g_stats[b * 4 + 0], sy = g_stats[b * 4 + 1];
        double sx2 = g_stats[b * 4 + 2], sy2 = g_stats[b * 4 + 3];
        float v;
        if (j == 55)      v = (float)(sx / N);
        else if (j == 56) v = (float)(sy / N);
        else if (j == 57) v = (float)sqrt(fmax(0.0, (sx2 - sx * sx / N) / (N - 1.0)));
        else if (j == 58) v = (float)sqrt(fmax(0.0, (sy2 - sy * sy / N) / (N - 1.0)));
        else              v = __int_as_float(g_magmax[b]);
        out[b * 60 + j] = v;
    }
}

extern "C" void kernel_launch(void* const* d_in, const int* in_sizes, int n_in,
                              void* d_out, int out_size) {
    (void)in_sizes; (void)n_in; (void)out_size;
    const float* x = (const float*)d_in[0];
    float* out = (float*)d_out;

    init_kernel<<<1, 1024>>>();
    row_fft_kernel<<<BATCH * H / 4, 128>>>(x);
    transpose_kernel<<<dim3(17, H / 32, BATCH), dim3(32, 8)>>>();
    col_fft_kernel<<<BATCH * WR / 2, 128>>>();
    statsx_kernel<<<dim3(64, BATCH), 256>>>();
    gemm_kernel<<<1184, 128>>>();
    finalize_kernel<<<BATCH, 64>>>(out);
}

// round 9
// speedup vs baseline: 1.2496x; 1.2496x over previous
#include <cuda_runtime.h>
#include <math.h>

#define BATCH 32
#define H 1024
#define W 1024
#define WR 513
#define NPIX (WR * H)
#define TP 56
#define TWO_PI 6.28318530717958647692f

#define PADI(e) ((e) + 5 * ((e) >> 5))
#define FFT_SM 1184

__device__ float2 g_bufA[(size_t)BATCH * H * WR];   /* row-fft out [b][r][c]; later pu [b][c][r] floats */
__device__ float2 g_bufB[(size_t)BATCH * WR * H];   /* transposed [b][c][r] */
__device__ float2 g_tw[1024];
__device__ float  g_coeff[BATCH * TP];
__device__ double g_stats[BATCH * 4];   /* sgx, sgy, sgx2, sgy2 */
__device__ int    g_magmax[BATCH];
__device__ int    g_maskcnt;

__global__ void init_kernel() {
    int t = threadIdx.x;   /* 1024 threads */
    float s, c;
    sincospif(-(float)t / 512.0f, &s, &c);
    g_tw[t] = make_float2(c, s);
    for (int i = t; i < BATCH * TP; i += 1024) g_coeff[i] = 0.0f;
    if (t < BATCH * 4) g_stats[t] = 0.0;
    if (t < BATCH)     g_magmax[t] = 0;
    if (t == 0)        g_maskcnt = 0;
}

/* DFT-16 fully in registers. */
__device__ __forceinline__ void dft16(float* vr, float* vi) {
    const float C1 = 0.92387953251128675613f;
    const float S1 = 0.38268343236508977173f;
    const float C2 = 0.70710678118654752440f;
    float tr[4][4], ti[4][4];
#pragma unroll
    for (int a = 0; a < 4; ++a) {
        float x0r = vr[a],      x0i = vi[a];
        float x1r = vr[a + 4],  x1i = vi[a + 4];
        float x2r = vr[a + 8],  x2i = vi[a + 8];
        float x3r = vr[a + 12], x3i = vi[a + 12];
        float s0r = x0r + x2r, s0i = x0i + x2i;
        float d0r = x0r - x2r, d0i = x0i - x2i;
        float s1r = x1r + x3r, s1i = x1i + x3i;
        float d1r = x1r - x3r, d1i = x1i - x3i;
        tr[a][0] = s0r + s1r; ti[a][0] = s0i + s1i;
        tr[a][1] = d0r + d1i; ti[a][1] = d0i - d1r;
        tr[a][2] = s0r - s1r; ti[a][2] = s0i - s1i;
        tr[a][3] = d0r - d1i; ti[a][3] = d0i + d1r;
    }
#pragma unroll
    for (int a = 1; a < 4; ++a) {
#pragma unroll
        for (int c = 1; c < 4; ++c) {
            int k = a * c;
            float wr, wi;
            if (k == 1)      { wr =  C1; wi = -S1; }
            else if (k == 2) { wr =  C2; wi = -C2; }
            else if (k == 3) { wr =  S1; wi = -C1; }
            else if (k == 4) { wr = 0.f; wi = -1.f; }
            else if (k == 6) { wr = -C2; wi = -C2; }
            else             { wr = -C1; wi =  S1; }
            float r = tr[a][c] * wr - ti[a][c] * wi;
            ti[a][c] = tr[a][c] * wi + ti[a][c] * wr;
            tr[a][c] = r;
        }
    }
#pragma unroll
    for (int c = 0; c < 4; ++c) {
        float s0r = tr[0][c] + tr[2][c], s0i = ti[0][c] + ti[2][c];
        float d0r = tr[0][c] - tr[2][c], d0i = ti[0][c] - ti[2][c];
        float s1r = tr[1][c] + tr[3][c], s1i = ti[1][c] + ti[3][c];
        float d1r = tr[1][c] - tr[3][c], d1i = ti[1][c] - ti[3][c];
        vr[c]      = s0r + s1r; vi[c]      = s0i + s1i;
        vr[c + 4]  = d0r + d1i; vi[c + 4]  = d0i - d1r;
        vr[c + 8]  = s0r - s1r; vi[c + 8]  = s0i - s1i;
        vr[c + 12] = d0r - d1i; vi[c + 12] = d0i + d1r;
    }
}

__device__ __forceinline__ void fft_stages01(float* vr, float* vi,
                                             float* SR, float* SI, int t) {
    dft16(vr, vi);
#pragma unroll
    for (int k = 0; k < 16; ++k) {
        int e = PADI(16 * t + k);
        SR[e] = vr[k]; SI[e] = vi[k];
    }
    __syncthreads();
#pragma unroll
    for (int m = 0; m < 16; ++m) {
        int e = PADI(t + 64 * m);
        vr[m] = SR[e]; vi[m] = SI[e];
    }
    int jm = t & 15;
#pragma unroll
    for (int m = 1; m < 16; ++m) {
        float2 w = g_tw[4 * m * jm];
        float r = vr[m] * w.x - vi[m] * w.y;
        vi[m] = vr[m] * w.y + vi[m] * w.x;
        vr[m] = r;
    }
    dft16(vr, vi);
    __syncthreads();
    int base1 = (t >> 4) * 256 + jm;
#pragma unroll
    for (int k = 0; k < 16; ++k) {
        int e = PADI(base1 + 16 * k);
        SR[e] = vr[k]; SI[e] = vi[k];
    }
    __syncthreads();
}

__device__ __forceinline__ void fft_stage2(const float* SR, const float* SI,
                                           int j, float* yr, float* yi) {
    float ar[4], ai[4];
#pragma unroll
    for (int m = 0; m < 4; ++m) {
        int e = PADI(j + 256 * m);
        ar[m] = SR[e]; ai[m] = SI[e];
    }
#pragma unroll
    for (int m = 1; m < 4; ++m) {
        float2 w = g_tw[m * j];
        float r = ar[m] * w.x - ai[m] * w.y;
        ai[m] = ar[m] * w.y + ai[m] * w.x;
        ar[m] = r;
    }
    float s0r = ar[0] + ar[2], s0i = ai[0] + ai[2];
    float d0r = ar[0] - ar[2], d0i = ai[0] - ai[2];
    float s1r = ar[1] + ar[3], s1i = ai[1] + ai[3];
    float d1r = ar[1] - ar[3], d1i = ai[1] - ai[3];
    yr[0] = s0r + s1r; yi[0] = s0i + s1i;
    yr[1] = d0r + d1i; yi[1] = d0i - d1r;
    yr[2] = s0r - s1r; yi[2] = s0i - s1i;
    yr[3] = d0r - d1i; yi[3] = d0i + d1r;
}

/* Two real rows packed per FFT; 2 FFTs per block; row-major coalesced output. */
__global__ void __launch_bounds__(128) row_fft_kernel(const float* __restrict__ x) {
    __shared__ float smr[2][FFT_SM], smi[2][FFT_SM];
    int f = threadIdx.x >> 6;
    int t = threadIdx.x & 63;
    int pr = blockIdx.x * 2 + f;
    float* SR = smr[f]; float* SI = smi[f];
    const float* rowA = x + (size_t)(2 * pr) * W;
    const float* rowB = rowA + W;
    float vr[16], vi[16];
#pragma unroll
    for (int m = 0; m < 16; ++m) {
        int idx = t + 64 * m;
        vr[m] = rowA[idx]; vi[m] = rowB[idx];
    }
    fft_stages01(vr, vi, SR, SI, t);
#pragma unroll
    for (int u = 0; u < 4; ++u) {
        int j = t + 64 * u;
        float yr[4], yi[4];
        fft_stage2(SR, SI, j, yr, yi);
#pragma unroll
        for (int k = 0; k < 4; ++k) {
            int e = PADI(j + 256 * k);
            SR[e] = yr[k]; SI[e] = yi[k];
        }
    }
    __syncthreads();
    float2* outA = g_bufA + (size_t)(2 * pr) * WR;
    float2* outB = outA + WR;
    for (int c = t; c < WR; c += 64) {
        int cn = (1024 - c) & 1023;
        float Zcr = SR[PADI(c)],  Zci = SI[PADI(c)];
        float Znr = SR[PADI(cn)], Zni = SI[PADI(cn)];
        float ar = 0.5f * (Zcr + Znr);
        float ai = 0.5f * (Zci - Zni);
        float dr = Zcr - Znr;
        float di = Zci + Zni;
        outA[c] = make_float2(ar, ai);
        outB[c] = make_float2(0.5f * di, -0.5f * dr);
    }
}

__global__ void transpose_kernel() {
    __shared__ float2 tile[32][33];
    int b  = blockIdx.z;
    int c0 = blockIdx.x * 32;
    int r0 = blockIdx.y * 32;
    int tx = threadIdx.x, ty = threadIdx.y;
    const float2* A = g_bufA + (size_t)b * H * WR;
    float2*       B = g_bufB + (size_t)b * WR * H;
#pragma unroll
    for (int i = ty; i < 32; i += 8) {
        int r = r0 + i, c = c0 + tx;
        if (c < WR) tile[i][tx] = A[(size_t)r * WR + c];
    }
    __syncthreads();
#pragma unroll
    for (int i = ty; i < 32; i += 8) {
        int c = c0 + i, r = r0 + tx;
        if (c < WR) B[(size_t)c * H + r] = tile[tx][i];
    }
}

/* 2 FFTs per block; epilogue: pu write, magnitude max, fused grad-y stats. */
__global__ void __launch_bounds__(128) col_fft_kernel() {
    __shared__ float smr[2][FFT_SM], smi[2][FFT_SM];
    __shared__ float sred[4], sgy[4], sgy2[4];
    int f = threadIdx.x >> 6;
    int t = threadIdx.x & 63;
    int blk = blockIdx.x * 2 + f;          /* b*WR + c */
    float* SR = smr[f]; float* SI = smi[f];
    const float2* in = g_bufB + (size_t)blk * H;
    float vr[16], vi[16];
#pragma unroll
    for (int m = 0; m < 16; ++m) {
        float2 z = in[t + 64 * m];
        vr[m] = z.x; vi[m] = z.y;
    }
    fft_stages01(vr, vi, SR, SI, t);

    float* pu = (float*)g_bufA;
    size_t outb = (size_t)blk * H;
    float maxm2 = 0.0f;
    float phv[16];
#pragma unroll
    for (int u = 0; u < 4; ++u) {
        int j = t + 64 * u;
        float yr[4], yi[4];
        fft_stage2(SR, SI, j, yr, yi);
#pragma unroll
        for (int k = 0; k < 4; ++k) {
            float m2 = fmaf(yr[k], yr[k], yi[k] * yi[k]);
            maxm2 = fmaxf(maxm2, m2);
            float ph = atan2f(yi[k], yr[k]);
            if (ph < 0.0f) ph += TWO_PI;
            phv[u + 4 * k] = ph;
            SR[PADI(j + 256 * k)] = ph;   /* in-place: thread-private slot set */
            pu[outb + j + 256 * k] = ph;
        }
    }
    __syncthreads();

    /* grad-y (along r) stats from smem phase column */
    float sy = 0.0f, sy2 = 0.0f;
#pragma unroll
    for (int s = 0; s < 16; ++s) {
        int r = t + 64 * s;
        float pc = phv[s];
        float gy;
        if (r == 0)          gy = SR[PADI(1)] - pc;
        else if (r == 1023)  gy = pc - SR[PADI(1022)];
        else                 gy = 0.5f * (SR[PADI(r + 1)] - SR[PADI(r - 1)]);
        sy += gy;
        sy2 = fmaf(gy, gy, sy2);
    }
#pragma unroll
    for (int o = 16; o; o >>= 1) {
        maxm2 = fmaxf(maxm2, __shfl_xor_sync(0xffffffffu, maxm2, o));
        sy  += __shfl_xor_sync(0xffffffffu, sy,  o);
        sy2 += __shfl_xor_sync(0xffffffffu, sy2, o);
    }
    int w = threadIdx.x >> 5;
    if ((threadIdx.x & 31) == 0) { sred[w] = maxm2; sgy[w] = sy; sgy2[w] = sy2; }
    __syncthreads();
    if (t == 0) {
        int b = blk / WR;
        float mm = fmaxf(sred[2 * f], sred[2 * f + 1]);
        atomicMax(&g_magmax[b], __float_as_int(sqrtf(mm)));
        atomicAdd(&g_stats[b * 4 + 1], (double)(sgy[2 * f] + sgy[2 * f + 1]));
        atomicAdd(&g_stats[b * 4 + 3], (double)(sgy2[2 * f] + sgy2[2 * f + 1]));
    }
}

/* grad-x only stats (gy fused into col_fft) */
__global__ void __launch_bounds__(256) statsx_kernel() {
    int b = blockIdx.y;
    const float4* pu4 = (const float4*)((const float*)g_bufA + (size_t)b * NPIX);
    float sx = 0.0f, sx2 = 0.0f;
    const int NQ = NPIX / 4;
    for (int q = blockIdx.x * 256 + threadIdx.x; q < NQ; q += gridDim.x * 256) {
        int c = q >> 8;
        float4 up, dn; float fac;
        if (c == 0)          { dn = pu4[q + 256]; up = pu4[q];       fac = 1.0f; }
        else if (c == WR - 1){ up = pu4[q - 256]; dn = pu4[q];       fac = 1.0f; }
        else                 { up = pu4[q - 256]; dn = pu4[q + 256]; fac = 0.5f; }
        float g0 = fac * (dn.x - up.x);
        float g1 = fac * (dn.y - up.y);
        float g2 = fac * (dn.z - up.z);
        float g3 = fac * (dn.w - up.w);
        sx += g0 + g1 + g2 + g3;
        sx2 = fmaf(g0, g0, fmaf(g1, g1, fmaf(g2, g2, fmaf(g3, g3, sx2))));
    }
    __shared__ double sbuf[8];
    double v2[2] = {(double)sx, (double)sx2};
#pragma unroll
    for (int qq = 0; qq < 2; ++qq) {
        double tt = v2[qq];
#pragma unroll
        for (int o = 16; o; o >>= 1) tt += __shfl_down_sync(0xffffffffu, tt, o);
        if ((threadIdx.x & 31) == 0) sbuf[threadIdx.x >> 5] = tt;
        __syncthreads();
        if (threadIdx.x < 8) {
            tt = sbuf[threadIdx.x];
#pragma unroll
            for (int o = 4; o; o >>= 1) tt += __shfl_down_sync(0xffu, tt, o);
            if (threadIdx.x == 0) atomicAdd(&g_stats[b * 4 + 2 * qq], tt);
        }
        __syncthreads();
    }
}

/* coeffs GEMM: R5's exact 2x7 register blocking, KC=64 */
#define KC 64
__global__ void __launch_bounds__(128) gemm_kernel() {
    __shared__ float pm_s[BATCH][KC + 4];
    __shared__ float z_s[TP][KC + 4];
    const float* pu = (const float*)g_bufA;
    int tid = threadIdx.x;
    int b0 = (tid >> 3) * 2;
    int t0 = (tid & 7) * 7;
    float acc[2][7];
#pragma unroll
    for (int a = 0; a < 2; ++a)
#pragma unroll
        for (int j = 0; j < 7; ++j) acc[a][j] = 0.0f;

    for (int k0 = blockIdx.x * KC; k0 < NPIX; k0 += gridDim.x * KC) {
        __syncthreads();
        if (tid < 64) {
            int pix = k0 + tid;
            int c = pix >> 10;
            int r = pix & 1023;
            float xg = (float)c * (1.0f / 256.0f) - 1.0f;
            float yg = (float)r * (2.0f / 1023.0f) - 1.0f;
            float rr = xg * xg + yg * yg;
            float rho = sqrtf(rr);
            float mk = (rho <= 1.0f) ? 1.0f : 0.0f;
            float inv = 1.0f / rho;
            float c1 = xg * inv, s1 = yg * inv;
            float q1 = rho, q2 = q1 * q1;
            float q3 = q2 * q1, q4 = q2 * q2, q5 = q3 * q2, q6 = q3 * q3;
            float q7 = q4 * q3, q8 = q4 * q4, q9 = q5 * q4;
            float c2 = c1 * c1 - s1 * s1, s2 = 2.0f * s1 * c1;
            float c3 = c1 * c2 - s1 * s2, s3 = s1 * c2 + c1 * s2;
            float c4 = c1 * c3 - s1 * s3, s4 = s1 * c3 + c1 * s3;
            float c5 = c1 * c4 - s1 * s4, s5 = s1 * c4 + c1 * s4;
            float c6 = c1 * c5 - s1 * s5, s6 = s1 * c5 + c1 * s5;
            float c7 = c1 * c6 - s1 * s6, s7 = s1 * c6 + c1 * s6;
            float c8 = c1 * c7 - s1 * s7, s8 = s1 * c7 + c1 * s7;
            float c9 = c1 * c8 - s1 * s8, s9 = s1 * c8 + c1 * s8;
#define ZST(tt, val) z_s[tt][tid] = (val) * mk
            ZST(0, 1.0f);
            ZST(1, q1 * s1);
            ZST(2, q1 * c1);
            ZST(3, q2 * s2);
            ZST(4, 2.0f * q2 - 1.0f);
            ZST(5, q2 * c2);
            ZST(6, q3 * s3);
            float R31 = 3.0f * q3 - 2.0f * q1;
            ZST(7, R31 * s1);
            ZST(8, R31 * c1);
            ZST(9, q3 * c3);
            ZST(10, q4 * s4);
            float R42 = 4.0f * q4 - 3.0f * q2;
            ZST(11, R42 * s2);
            ZST(12, 6.0f * q4 - 6.0f * q2 + 1.0f);
            ZST(13, R42 * c2);
            ZST(14, q4 * c4);
            ZST(15, q5 * s5);
            float R53 = 5.0f * q5 - 4.0f * q3;
            ZST(16, R53 * s3);
            float R51 = 10.0f * q5 - 12.0f * q3 + 3.0f * q1;
            ZST(17, R51 * s1);
            ZST(18, R51 * c1);
            ZST(19, R53 * c3);
            ZST(20, q5 * c5);
            ZST(21, q6 * s6);
            float R64 = 6.0f * q6 - 5.0f * q4;
            ZST(22, R64 * s4);
            float R62 = 15.0f * q6 - 20.0f * q4 + 6.0f * q2;
            ZST(23, R62 * s2);
            ZST(24, 20.0f * q6 - 30.0f * q4 + 12.0f * q2 - 1.0f);
            ZST(25, R62 * c2);
            ZST(26, R64 * c4);
            ZST(27, q6 * c6);
            ZST(28, q7 * s7);
            float R75 = 7.0f * q7 - 6.0f * q5;
            ZST(29, R75 * s5);
            float R73 = 21.0f * q7 - 30.0f * q5 + 10.0f * q3;
            ZST(30, R73 * s3);
            float R71 = 35.0f * q7 - 60.0f * q5 + 30.0f * q3 - 4.0f * q1;
            ZST(31, R71 * s1);
            ZST(32, R71 * c1);
            ZST(33, R73 * c3);
            ZST(34, R75 * c5);
            ZST(35, q7 * c7);
            ZST(36, q8 * s8);
            float R86 = 8.0f * q8 - 7.0f * q6;
            ZST(37, R86 * s6);
            float R84 = 28.0f * q8 - 42.0f * q6 + 15.0f * q4;
            ZST(38, R84 * s4);
            float R82 = 56.0f * q8 - 105.0f * q6 + 60.0f * q4 - 10.0f * q2;
            ZST(39, R82 * s2);
            ZST(40, 70.0f * q8 - 140.0f * q6 + 90.0f * q4 - 20.0f * q2 + 1.0f);
            ZST(41, R82 * c2);
            ZST(42, R84 * c4);
            ZST(43, R86 * c6);
            ZST(44, q8 * c8);
            ZST(45, q9 * s9);
            float R97 = 9.0f * q9 - 8.0f * q7;
            ZST(46, R97 * s7);
            float R95 = 36.0f * q9 - 56.0f * q7 + 21.0f * q5;
            ZST(47, R95 * s5);
            float R93 = 84.0f * q9 - 168.0f * q7 + 105.0f * q5 - 20.0f * q3;
            ZST(48, R93 * s3);
            float R91 = 126.0f * q9 - 280.0f * q7 + 210.0f * q5 - 60.0f * q3 + 5.0f * q1;
            ZST(49, R91 * s1);
            ZST(50, R91 * c1);
            ZST(51, R93 * c3);
            ZST(52, R95 * c5);
            ZST(53, R97 * c7);
            ZST(54, q9 * c9);
            z_s[55][tid] = 0.0f;
#undef ZST
            unsigned bal = __ballot_sync(0xffffffffu, mk > 0.5f);
            if ((tid & 31) == 0) atomicAdd(&g_maskcnt, __popc(bal));
        } else {
            int t = tid - 64;
#pragma unroll
            for (int row = 0; row < BATCH; ++row)
                pm_s[row][t] = pu[(size_t)row * NPIX + k0 + t];
        }
        __syncthreads();
#pragma unroll 8
        for (int kk = 0; kk < KC; kk += 4) {
            float4 a0 = *(const float4*)&pm_s[b0][kk];
            float4 a1 = *(const float4*)&pm_s[b0 + 1][kk];
#pragma unroll
            for (int j = 0; j < 7; ++j) {
                float4 zz = *(const float4*)&z_s[t0 + j][kk];
                acc[0][j] = fmaf(a0.x, zz.x, fmaf(a0.y, zz.y, fmaf(a0.z, zz.z, fmaf(a0.w, zz.w, acc[0][j]))));
                acc[1][j] = fmaf(a1.x, zz.x, fmaf(a1.y, zz.y, fmaf(a1.z, zz.z, fmaf(a1.w, zz.w, acc[1][j]))));
            }
        }
    }
#pragma unroll
    for (int j = 0; j < 7; ++j) {
        atomicAdd(&g_coeff[(b0)     * TP + t0 + j], acc[0][j]);
        atomicAdd(&g_coeff[(b0 + 1) * TP + t0 + j], acc[1][j]);
    }
}

__global__ void finalize_kernel(float* __restrict__ out) {
    int b = blockIdx.x;
    int j = threadIdx.x;
    if (j < 55) {
        out[b * 60 + j] = g_coeff[b * TP + j] / (float)g_maskcnt;
    } else if (j < 60) {
        double N = (double)NPIX;
        double sx = g_stats[b * 4 + 0], sy = g_stats[b * 4 + 1];
        double sx2 = g_stats[b * 4 + 2], sy2 = g_stats[b * 4 + 3];
        float v;
        if (j == 55)      v = (float)(sx / N);
        else if (j == 56) v = (float)(sy / N);
        else if (j == 57) v = (float)sqrt(fmax(0.0, (sx2 - sx * sx / N) / (N - 1.0)));
        else if (j == 58) v = (float)sqrt(fmax(0.0, (sy2 - sy * sy / N) / (N - 1.0)));
        else              v = __int_as_float(g_magmax[b]);
        out[b * 60 + j] = v;
    }
}

extern "C" void kernel_launch(void* const* d_in, const int* in_sizes, int n_in,
                              void* d_out, int out_size) {
    (void)in_sizes; (void)n_in; (void)out_size;
    const float* x = (const float*)d_in[0];
    float* out = (float*)d_out;

    init_kernel<<<1, 1024>>>();
    row_fft_kernel<<<BATCH * H / 4, 128>>>(x);
    transpose_kernel<<<dim3(17, H / 32, BATCH), dim3(32, 8)>>>();
    col_fft_kernel<<<BATCH * WR / 2, 128>>>();
    statsx_kernel<<<dim3(64, BATCH), 256>>>();
    gemm_kernel<<<592, 128>>>();
    finalize_kernel<<<BATCH, 64>>>(out);
}

// round 12
// speedup vs baseline: 1.3059x; 1.0450x over previous
#include <cuda_runtime.h>
#include <math.h>

#define BATCH 32
#define H 1024
#define W 1024
#define WR 513
#define NPIX (WR * H)
#define TP 56
#define TWO_PI 6.28318530717958647692f

#define PADI(e) ((e) + 5 * ((e) >> 5))
#define FFT_SM 1184

__device__ float2 g_bufA[(size_t)BATCH * H * WR];   /* row-fft out [b][r][c]; later pu [b][c][r] floats */
__device__ float2 g_bufB[(size_t)BATCH * WR * H];   /* transposed [b][c][r] */
__device__ float2 g_tw[1024];
__device__ float  g_coeff[BATCH * TP];
__device__ double g_stats[BATCH * 4];   /* sgx, sgy, sgx2, sgy2 */
__device__ int    g_magmax[BATCH];
__device__ int    g_maskcnt;

__global__ void init_kernel() {
    int t = threadIdx.x;   /* 1024 threads */
    float s, c;
    sincospif(-(float)t / 512.0f, &s, &c);
    g_tw[t] = make_float2(c, s);
    for (int i = t; i < BATCH * TP; i += 1024) g_coeff[i] = 0.0f;
    if (t < BATCH * 4) g_stats[t] = 0.0;
    if (t < BATCH)     g_magmax[t] = 0;
    if (t == 0)        g_maskcnt = 0;
}

/* atan2 -> [0, 2pi) unwrapped phase; minimax poly, max abs err ~1e-8 */
__device__ __forceinline__ float fast_phase(float y, float x) {
    float ax = fabsf(x), ay = fabsf(y);
    float mn = fminf(ax, ay), mx = fmaxf(ax, ay);
    float r = (mx == 0.0f) ? 0.0f : __fdividef(mn, mx);
    float a = r * r;
    float p = fmaf(a, -0.0040540580f, 0.0218612288f);
    p = fmaf(a, p, -0.0559098861f);
    p = fmaf(a, p, 0.0964200441f);
    p = fmaf(a, p, -0.1390853351f);
    p = fmaf(a, p, 0.1994653599f);
    p = fmaf(a, p, -0.3332985605f);
    p = fmaf(a, p, 0.9999993329f);
    float th = r * p;                                   /* atan in [0, pi/4] */
    if (ay > ax)    th = 1.57079632679489662f - th;
    if (x < 0.0f)   th = 3.14159265358979324f - th;     /* now in [0, pi] */
    if (y < 0.0f)   th = TWO_PI - th;
    return th;
}

/* DFT-16 fully in registers. */
__device__ __forceinline__ void dft16(float* vr, float* vi) {
    const float C1 = 0.92387953251128675613f;
    const float S1 = 0.38268343236508977173f;
    const float C2 = 0.70710678118654752440f;
    float tr[4][4], ti[4][4];
#pragma unroll
    for (int a = 0; a < 4; ++a) {
        float x0r = vr[a],      x0i = vi[a];
        float x1r = vr[a + 4],  x1i = vi[a + 4];
        float x2r = vr[a + 8],  x2i = vi[a + 8];
        float x3r = vr[a + 12], x3i = vi[a + 12];
        float s0r = x0r + x2r, s0i = x0i + x2i;
        float d0r = x0r - x2r, d0i = x0i - x2i;
        float s1r = x1r + x3r, s1i = x1i + x3i;
        float d1r = x1r - x3r, d1i = x1i - x3i;
        tr[a][0] = s0r + s1r; ti[a][0] = s0i + s1i;
        tr[a][1] = d0r + d1i; ti[a][1] = d0i - d1r;
        tr[a][2] = s0r - s1r; ti[a][2] = s0i - s1i;
        tr[a][3] = d0r - d1i; ti[a][3] = d0i + d1r;
    }
#pragma unroll
    for (int a = 1; a < 4; ++a) {
#pragma unroll
        for (int c = 1; c < 4; ++c) {
            int k = a * c;
            float wr, wi;
            if (k == 1)      { wr =  C1; wi = -S1; }
            else if (k == 2) { wr =  C2; wi = -C2; }
            else if (k == 3) { wr =  S1; wi = -C1; }
            else if (k == 4) { wr = 0.f; wi = -1.f; }
            else if (k == 6) { wr = -C2; wi = -C2; }
            else             { wr = -C1; wi =  S1; }
            float r = tr[a][c] * wr - ti[a][c] * wi;
            ti[a][c] = tr[a][c] * wi + ti[a][c] * wr;
            tr[a][c] = r;
        }
    }
#pragma unroll
    for (int c = 0; c < 4; ++c) {
        float s0r = tr[0][c] + tr[2][c], s0i = ti[0][c] + ti[2][c];
        float d0r = tr[0][c] - tr[2][c], d0i = ti[0][c] - ti[2][c];
        float s1r = tr[1][c] + tr[3][c], s1i = ti[1][c] + ti[3][c];
        float d1r = tr[1][c] - tr[3][c], d1i = ti[1][c] - ti[3][c];
        vr[c]      = s0r + s1r; vi[c]      = s0i + s1i;
        vr[c + 4]  = d0r + d1i; vi[c + 4]  = d0i - d1r;
        vr[c + 8]  = s0r - s1r; vi[c + 8]  = s0i - s1i;
        vr[c + 12] = d0r - d1i; vi[c + 12] = d0i + d1r;
    }
}

__device__ __forceinline__ void fft_stages01(float* vr, float* vi,
                                             float* SR, float* SI, int t) {
    dft16(vr, vi);
#pragma unroll
    for (int k = 0; k < 16; ++k) {
        int e = PADI(16 * t + k);
        SR[e] = vr[k]; SI[e] = vi[k];
    }
    __syncthreads();
#pragma unroll
    for (int m = 0; m < 16; ++m) {
        int e = PADI(t + 64 * m);
        vr[m] = SR[e]; vi[m] = SI[e];
    }
    int jm = t & 15;
#pragma unroll
    for (int m = 1; m < 16; ++m) {
        float2 w = g_tw[4 * m * jm];
        float r = vr[m] * w.x - vi[m] * w.y;
        vi[m] = vr[m] * w.y + vi[m] * w.x;
        vr[m] = r;
    }
    dft16(vr, vi);
    __syncthreads();
    int base1 = (t >> 4) * 256 + jm;
#pragma unroll
    for (int k = 0; k < 16; ++k) {
        int e = PADI(base1 + 16 * k);
        SR[e] = vr[k]; SI[e] = vi[k];
    }
    __syncthreads();
}

__device__ __forceinline__ void fft_stage2(const float* SR, const float* SI,
                                           int j, float* yr, float* yi) {
    float ar[4], ai[4];
#pragma unroll
    for (int m = 0; m < 4; ++m) {
        int e = PADI(j + 256 * m);
        ar[m] = SR[e]; ai[m] = SI[e];
    }
#pragma unroll
    for (int m = 1; m < 4; ++m) {
        float2 w = g_tw[m * j];
        float r = ar[m] * w.x - ai[m] * w.y;
        ai[m] = ar[m] * w.y + ai[m] * w.x;
        ar[m] = r;
    }
    float s0r = ar[0] + ar[2], s0i = ai[0] + ai[2];
    float d0r = ar[0] - ar[2], d0i = ai[0] - ai[2];
    float s1r = ar[1] + ar[3], s1i = ai[1] + ai[3];
    float d1r = ar[1] - ar[3], d1i = ai[1] - ai[3];
    yr[0] = s0r + s1r; yi[0] = s0i + s1i;
    yr[1] = d0r + d1i; yi[1] = d0i - d1r;
    yr[2] = s0r - s1r; yi[2] = s0i - s1i;
    yr[3] = d0r - d1i; yi[3] = d0i + d1r;
}

/* Two real rows packed per FFT; 2 FFTs per block; row-major coalesced output. */
__global__ void __launch_bounds__(128) row_fft_kernel(const float* __restrict__ x) {
    __shared__ float smr[2][FFT_SM], smi[2][FFT_SM];
    int f = threadIdx.x >> 6;
    int t = threadIdx.x & 63;
    int pr = blockIdx.x * 2 + f;
    float* SR = smr[f]; float* SI = smi[f];
    const float* rowA = x + (size_t)(2 * pr) * W;
    const float* rowB = rowA + W;
    float vr[16], vi[16];
#pragma unroll
    for (int m = 0; m < 16; ++m) {
        int idx = t + 64 * m;
        vr[m] = rowA[idx]; vi[m] = rowB[idx];
    }
    fft_stages01(vr, vi, SR, SI, t);
#pragma unroll
    for (int u = 0; u < 4; ++u) {
        int j = t + 64 * u;
        float yr[4], yi[4];
        fft_stage2(SR, SI, j, yr, yi);
#pragma unroll
        for (int k = 0; k < 4; ++k) {
            int e = PADI(j + 256 * k);
            SR[e] = yr[k]; SI[e] = yi[k];
        }
    }
    __syncthreads();
    float2* outA = g_bufA + (size_t)(2 * pr) * WR;
    float2* outB = outA + WR;
    for (int c = t; c < WR; c += 64) {
        int cn = (1024 - c) & 1023;
        float Zcr = SR[PADI(c)],  Zci = SI[PADI(c)];
        float Znr = SR[PADI(cn)], Zni = SI[PADI(cn)];
        float ar = 0.5f * (Zcr + Znr);
        float ai = 0.5f * (Zci - Zni);
        float dr = Zcr - Znr;
        float di = Zci + Zni;
        outA[c] = make_float2(ar, ai);
        outB[c] = make_float2(0.5f * di, -0.5f * dr);
    }
}

__global__ void transpose_kernel() {
    __shared__ float2 tile[32][33];
    int b  = blockIdx.z;
    int c0 = blockIdx.x * 32;
    int r0 = blockIdx.y * 32;
    int tx = threadIdx.x, ty = threadIdx.y;
    const float2* A = g_bufA + (size_t)b * H * WR;
    float2*       B = g_bufB + (size_t)b * WR * H;
#pragma unroll
    for (int i = ty; i < 32; i += 8) {
        int r = r0 + i, c = c0 + tx;
        if (c < WR) tile[i][tx] = A[(size_t)r * WR + c];
    }
    __syncthreads();
#pragma unroll
    for (int i = ty; i < 32; i += 8) {
        int c = c0 + i, r = r0 + tx;
        if (c < WR) B[(size_t)c * H + r] = tile[tx][i];
    }
}

/* 2 FFTs per block; epilogue: pu write, magnitude max, fused grad-y stats. */
__global__ void __launch_bounds__(128) col_fft_kernel() {
    __shared__ float smr[2][FFT_SM], smi[2][FFT_SM];
    __shared__ float sred[4], sgy[4], sgy2[4];
    int f = threadIdx.x >> 6;
    int t = threadIdx.x & 63;
    int blk = blockIdx.x * 2 + f;          /* b*WR + c */
    float* SR = smr[f]; float* SI = smi[f];
    const float2* in = g_bufB + (size_t)blk * H;
    float vr[16], vi[16];
#pragma unroll
    for (int m = 0; m < 16; ++m) {
        float2 z = in[t + 64 * m];
        vr[m] = z.x; vi[m] = z.y;
    }
    fft_stages01(vr, vi, SR, SI, t);

    float* pu = (float*)g_bufA;
    size_t outb = (size_t)blk * H;
    float maxm2 = 0.0f;
    float phv[16];
#pragma unroll
    for (int u = 0; u < 4; ++u) {
        int j = t + 64 * u;
        float yr[4], yi[4];
        fft_stage2(SR, SI, j, yr, yi);
#pragma unroll
        for (int k = 0; k < 4; ++k) {
            float m2 = fmaf(yr[k], yr[k], yi[k] * yi[k]);
            maxm2 = fmaxf(maxm2, m2);
            float ph = fast_phase(yi[k], yr[k]);
            phv[u + 4 * k] = ph;
            SR[PADI(j + 256 * k)] = ph;   /* in-place: thread-private slot set */
            pu[outb + j + 256 * k] = ph;
        }
    }
    __syncthreads();

    /* grad-y (along r) stats from smem phase column */
    float sy = 0.0f, sy2 = 0.0f;
#pragma unroll
    for (int s = 0; s < 16; ++s) {
        int r = t + 64 * s;
        float pc = phv[s];
        float gy;
        if (r == 0)          gy = SR[PADI(1)] - pc;
        else if (r == 1023)  gy = pc - SR[PADI(1022)];
        else                 gy = 0.5f * (SR[PADI(r + 1)] - SR[PADI(r - 1)]);
        sy += gy;
        sy2 = fmaf(gy, gy, sy2);
    }
#pragma unroll
    for (int o = 16; o; o >>= 1) {
        maxm2 = fmaxf(maxm2, __shfl_xor_sync(0xffffffffu, maxm2, o));
        sy  += __shfl_xor_sync(0xffffffffu, sy,  o);
        sy2 += __shfl_xor_sync(0xffffffffu, sy2, o);
    }
    int w = threadIdx.x >> 5;
    if ((threadIdx.x & 31) == 0) { sred[w] = maxm2; sgy[w] = sy; sgy2[w] = sy2; }
    __syncthreads();
    if (t == 0) {
        int b = blk / WR;
        float mm = fmaxf(sred[2 * f], sred[2 * f + 1]);
        atomicMax(&g_magmax[b], __float_as_int(sqrtf(mm)));
        atomicAdd(&g_stats[b * 4 + 1], (double)(sgy[2 * f] + sgy[2 * f + 1]));
        atomicAdd(&g_stats[b * 4 + 3], (double)(sgy2[2 * f] + sgy2[2 * f + 1]));
    }
}

/* grad-x only stats (gy fused into col_fft) */
__global__ void __launch_bounds__(256) statsx_kernel() {
    int b = blockIdx.y;
    const float4* pu4 = (const float4*)((const float*)g_bufA + (size_t)b * NPIX);
    float sx = 0.0f, sx2 = 0.0f;
    const int NQ = NPIX / 4;
    for (int q = blockIdx.x * 256 + threadIdx.x; q < NQ; q += gridDim.x * 256) {
        int c = q >> 8;
        float4 up, dn; float fac;
        if (c == 0)          { dn = pu4[q + 256]; up = pu4[q];       fac = 1.0f; }
        else if (c == WR - 1){ up = pu4[q - 256]; dn = pu4[q];       fac = 1.0f; }
        else                 { up = pu4[q - 256]; dn = pu4[q + 256]; fac = 0.5f; }
        float g0 = fac * (dn.x - up.x);
        float g1 = fac * (dn.y - up.y);
        float g2 = fac * (dn.z - up.z);
        float g3 = fac * (dn.w - up.w);
        sx += g0 + g1 + g2 + g3;
        sx2 = fmaf(g0, g0, fmaf(g1, g1, fmaf(g2, g2, fmaf(g3, g3, sx2))));
    }
    __shared__ double sbuf[8];
    double v2[2] = {(double)sx, (double)sx2};
#pragma unroll
    for (int qq = 0; qq < 2; ++qq) {
        double tt = v2[qq];
#pragma unroll
        for (int o = 16; o; o >>= 1) tt += __shfl_down_sync(0xffffffffu, tt, o);
        if ((threadIdx.x & 31) == 0) sbuf[threadIdx.x >> 5] = tt;
        __syncthreads();
        if (threadIdx.x < 8) {
            tt = sbuf[threadIdx.x];
#pragma unroll
            for (int o = 4; o; o >>= 1) tt += __shfl_down_sync(0xffu, tt, o);
            if (threadIdx.x == 0) atomicAdd(&g_stats[b * 4 + 2 * qq], tt);
        }
        __syncthreads();
    }
}

/* coeffs GEMM: 2x7 register blocking, KC=128, all threads compute Z then load pm */
#define KC 128
__global__ void __launch_bounds__(128) gemm_kernel() {
    __shared__ float pm_s[BATCH][KC + 4];
    __shared__ float z_s[TP][KC + 4];
    const float* pu = (const float*)g_bufA;
    int tid = threadIdx.x;
    int b0 = (tid >> 3) * 2;
    int t0 = (tid & 7) * 7;
    float acc[2][7];
#pragma unroll
    for (int a = 0; a < 2; ++a)
#pragma unroll
        for (int j = 0; j < 7; ++j) acc[a][j] = 0.0f;

    for (int k0 = blockIdx.x * KC; k0 < NPIX; k0 += gridDim.x * KC) {
        __syncthreads();
        {
            int pix = k0 + tid;
            int c = pix >> 10;
            int r = pix & 1023;
            float xg = (float)c * (1.0f / 256.0f) - 1.0f;
            float yg = (float)r * (2.0f / 1023.0f) - 1.0f;
            float rr = xg * xg + yg * yg;
            float rho = sqrtf(rr);
            float mk = (rho <= 1.0f) ? 1.0f : 0.0f;
            float inv = 1.0f / rho;
            float c1 = xg * inv, s1 = yg * inv;
            float q1 = rho, q2 = q1 * q1;
            float q3 = q2 * q1, q4 = q2 * q2, q5 = q3 * q2, q6 = q3 * q3;
            float q7 = q4 * q3, q8 = q4 * q4, q9 = q5 * q4;
            float c2 = c1 * c1 - s1 * s1, s2 = 2.0f * s1 * c1;
            float c3 = c1 * c2 - s1 * s2, s3 = s1 * c2 + c1 * s2;
            float c4 = c1 * c3 - s1 * s3, s4 = s1 * c3 + c1 * s3;
            float c5 = c1 * c4 - s1 * s4, s5 = s1 * c4 + c1 * s4;
            float c6 = c1 * c5 - s1 * s5, s6 = s1 * c5 + c1 * s5;
            float c7 = c1 * c6 - s1 * s6, s7 = s1 * c6 + c1 * s6;
            float c8 = c1 * c7 - s1 * s7, s8 = s1 * c7 + c1 * s7;
            float c9 = c1 * c8 - s1 * s8, s9 = s1 * c8 + c1 * s8;
#define ZST(tt, val) z_s[tt][tid] = (val) * mk
            ZST(0, 1.0f);
            ZST(1, q1 * s1);
            ZST(2, q1 * c1);
            ZST(3, q2 * s2);
            ZST(4, 2.0f * q2 - 1.0f);
            ZST(5, q2 * c2);
            ZST(6, q3 * s3);
            float R31 = 3.0f * q3 - 2.0f * q1;
            ZST(7, R31 * s1);
            ZST(8, R31 * c1);
            ZST(9, q3 * c3);
            ZST(10, q4 * s4);
            float R42 = 4.0f * q4 - 3.0f * q2;
            ZST(11, R42 * s2);
            ZST(12, 6.0f * q4 - 6.0f * q2 + 1.0f);
            ZST(13, R42 * c2);
            ZST(14, q4 * c4);
            ZST(15, q5 * s5);
            float R53 = 5.0f * q5 - 4.0f * q3;
            ZST(16, R53 * s3);
            float R51 = 10.0f * q5 - 12.0f * q3 + 3.0f * q1;
            ZST(17, R51 * s1);
            ZST(18, R51 * c1);
            ZST(19, R53 * c3);
            ZST(20, q5 * c5);
            ZST(21, q6 * s6);
            float R64 = 6.0f * q6 - 5.0f * q4;
            ZST(22, R64 * s4);
            float R62 = 15.0f * q6 - 20.0f * q4 + 6.0f * q2;
            ZST(23, R62 * s2);
            ZST(24, 20.0f * q6 - 30.0f * q4 + 12.0f * q2 - 1.0f);
            ZST(25, R62 * c2);
            ZST(26, R64 * c4);
            ZST(27, q6 * c6);
            ZST(28, q7 * s7);
            float R75 = 7.0f * q7 - 6.0f * q5;
            ZST(29, R75 * s5);
            float R73 = 21.0f * q7 - 30.0f * q5 + 10.0f * q3;
            ZST(30, R73 * s3);
            float R71 = 35.0f * q7 - 60.0f * q5 + 30.0f * q3 - 4.0f * q1;
            ZST(31, R71 * s1);
            ZST(32, R71 * c1);
            ZST(33, R73 * c3);
            ZST(34, R75 * c5);
            ZST(35, q7 * c7);
            ZST(36, q8 * s8);
            float R86 = 8.0f * q8 - 7.0f * q6;
            ZST(37, R86 * s6);
            float R84 = 28.0f * q8 - 42.0f * q6 + 15.0f * q4;
            ZST(38, R84 * s4);
            float R82 = 56.0f * q8 - 105.0f * q6 + 60.0f * q4 - 10.0f * q2;
            ZST(39, R82 * s2);
            ZST(40, 70.0f * q8 - 140.0f * q6 + 90.0f * q4 - 20.0f * q2 + 1.0f);
            ZST(41, R82 * c2);
            ZST(42, R84 * c4);
            ZST(43, R86 * c6);
            ZST(44, q8 * c8);
            ZST(45, q9 * s9);
            float R97 = 9.0f * q9 - 8.0f * q7;
            ZST(46, R97 * s7);
            float R95 = 36.0f * q9 - 56.0f * q7 + 21.0f * q5;
            ZST(47, R95 * s5);
            float R93 = 84.0f * q9 - 168.0f * q7 + 105.0f * q5 - 20.0f * q3;
            ZST(48, R93 * s3);
            float R91 = 126.0f * q9 - 280.0f * q7 + 210.0f * q5 - 60.0f * q3 + 5.0f * q1;
            ZST(49, R91 * s1);
            ZST(50, R91 * c1);
            ZST(51, R93 * c3);
            ZST(52, R95 * c5);
            ZST(53, R97 * c7);
            ZST(54, q9 * c9);
            z_s[55][tid] = 0.0f;
#undef ZST
            unsigned bal = __ballot_sync(0xffffffffu, mk > 0.5f);
            if ((tid & 31) == 0) atomicAdd(&g_maskcnt, __popc(bal));
        }
#pragma unroll
        for (int row = 0; row < BATCH; ++row)
            pm_s[row][tid] = pu[(size_t)row * NPIX + k0 + tid];
        __syncthreads();
#pragma unroll 8
        for (int kk = 0; kk < KC; kk += 4) {
            float4 a0 = *(const float4*)&pm_s[b0][kk];
            float4 a1 = *(const float4*)&pm_s[b0 + 1][kk];
#pragma unroll
            for (int j = 0; j < 7; ++j) {
                float4 zz = *(const float4*)&z_s[t0 + j][kk];
                acc[0][j] = fmaf(a0.x, zz.x, fmaf(a0.y, zz.y, fmaf(a0.z, zz.z, fmaf(a0.w, zz.w, acc[0][j]))));
                acc[1][j] = fmaf(a1.x, zz.x, fmaf(a1.y, zz.y, fmaf(a1.z, zz.z, fmaf(a1.w, zz.w, acc[1][j]))));
            }
        }
    }
#pragma unroll
    for (int j = 0; j < 7; ++j) {
        atomicAdd(&g_coeff[(b0)     * TP + t0 + j], acc[0][j]);
        atomicAdd(&g_coeff[(b0 + 1) * TP + t0 + j], acc[1][j]);
    }
}

__global__ void finalize_kernel(float* __restrict__ out) {
    int b = blockIdx.x;
    int j = threadIdx.x;
    if (j < 55) {
        out[b * 60 + j] = g_coeff[b * TP + j] / (float)g_maskcnt;
    } else if (j < 60) {
        double N = (double)NPIX;
        double sx = g_stats[b * 4 + 0], sy = g_stats[b * 4 + 1];
        double sx2 = g_stats[b * 4 + 2], sy2 = g_stats[b * 4 + 3];
        float v;
        if (j == 55)      v = (float)(sx / N);
        else if (j == 56) v = (float)(sy / N);
        else if (j == 57) v = (float)sqrt(fmax(0.0, (sx2 - sx * sx / N) / (N - 1.0)));
        else if (j == 58) v = (float)sqrt(fmax(0.0, (sy2 - sy * sy / N) / (N - 1.0)));
        else              v = __int_as_float(g_magmax[b]);
        out[b * 60 + j] = v;
    }
}

extern "C" void kernel_launch(void* const* d_in, const int* in_sizes, int n_in,
                              void* d_out, int out_size) {
    (void)in_sizes; (void)n_in; (void)out_size;
    const float* x = (const float*)d_in[0];
    float* out = (float*)d_out;

    init_kernel<<<1, 1024>>>();
    row_fft_kernel<<<BATCH * H / 4, 128>>>(x);
    transpose_kernel<<<dim3(17, H / 32, BATCH), dim3(32, 8)>>>();
    col_fft_kernel<<<BATCH * WR / 2, 128>>>();
    statsx_kernel<<<dim3(64, BATCH), 256>>>();
    gemm_kernel<<<592, 128>>>();
    finalize_kernel<<<BATCH, 64>>>(out);
}

// round 13
// speedup vs baseline: 1.3136x; 1.0059x over previous
#include <cuda_runtime.h>
#include <math.h>

#define BATCH 32
#define H 1024
#define W 1024
#define WR 513
#define NPIX (WR * H)
#define TP 56
#define TWO_PI 6.28318530717958647692f

#define PADI(e) ((e) + 5 * ((e) >> 5))
#define FFT_SM 1184

__device__ float2 g_bufA[(size_t)BATCH * H * WR];   /* row-fft out [b][r][c]; later pu [b][c][r] floats */
__device__ float2 g_bufB[(size_t)BATCH * WR * H];   /* transposed [b][c][r] */
__device__ float2 g_tw[1024];
__device__ float  g_coeff[BATCH * TP];
__device__ double g_stats[BATCH * 4];   /* sgx, sgy, sgx2, sgy2 */
__device__ int    g_magmax[BATCH];
__device__ int    g_maskcnt;

__global__ void init_kernel() {
    int t = threadIdx.x;   /* 1024 threads */
    float s, c;
    sincospif(-(float)t / 512.0f, &s, &c);
    g_tw[t] = make_float2(c, s);
    for (int i = t; i < BATCH * TP; i += 1024) g_coeff[i] = 0.0f;
    if (t < BATCH * 4) g_stats[t] = 0.0;
    if (t < BATCH)     g_magmax[t] = 0;
    if (t == 0)        g_maskcnt = 0;
}

/* atan2 -> [0, 2pi) unwrapped phase; minimax poly, max abs err ~1e-8 */
__device__ __forceinline__ float fast_phase(float y, float x) {
    float ax = fabsf(x), ay = fabsf(y);
    float mn = fminf(ax, ay), mx = fmaxf(ax, ay);
    float r = (mx == 0.0f) ? 0.0f : __fdividef(mn, mx);
    float a = r * r;
    float p = fmaf(a, -0.0040540580f, 0.0218612288f);
    p = fmaf(a, p, -0.0559098861f);
    p = fmaf(a, p, 0.0964200441f);
    p = fmaf(a, p, -0.1390853351f);
    p = fmaf(a, p, 0.1994653599f);
    p = fmaf(a, p, -0.3332985605f);
    p = fmaf(a, p, 0.9999993329f);
    float th = r * p;                                   /* atan in [0, pi/4] */
    if (ay > ax)    th = 1.57079632679489662f - th;
    if (x < 0.0f)   th = 3.14159265358979324f - th;     /* now in [0, pi] */
    if (y < 0.0f)   th = TWO_PI - th;
    return th;
}

/* DFT-16 fully in registers. */
__device__ __forceinline__ void dft16(float* vr, float* vi) {
    const float C1 = 0.92387953251128675613f;
    const float S1 = 0.38268343236508977173f;
    const float C2 = 0.70710678118654752440f;
    float tr[4][4], ti[4][4];
#pragma unroll
    for (int a = 0; a < 4; ++a) {
        float x0r = vr[a],      x0i = vi[a];
        float x1r = vr[a + 4],  x1i = vi[a + 4];
        float x2r = vr[a + 8],  x2i = vi[a + 8];
        float x3r = vr[a + 12], x3i = vi[a + 12];
        float s0r = x0r + x2r, s0i = x0i + x2i;
        float d0r = x0r - x2r, d0i = x0i - x2i;
        float s1r = x1r + x3r, s1i = x1i + x3i;
        float d1r = x1r - x3r, d1i = x1i - x3i;
        tr[a][0] = s0r + s1r; ti[a][0] = s0i + s1i;
        tr[a][1] = d0r + d1i; ti[a][1] = d0i - d1r;
        tr[a][2] = s0r - s1r; ti[a][2] = s0i - s1i;
        tr[a][3] = d0r - d1i; ti[a][3] = d0i + d1r;
    }
#pragma unroll
    for (int a = 1; a < 4; ++a) {
#pragma unroll
        for (int c = 1; c < 4; ++c) {
            int k = a * c;
            float wr, wi;
            if (k == 1)      { wr =  C1; wi = -S1; }
            else if (k == 2) { wr =  C2; wi = -C2; }
            else if (k == 3) { wr =  S1; wi = -C1; }
            else if (k == 4) { wr = 0.f; wi = -1.f; }
            else if (k == 6) { wr = -C2; wi = -C2; }
            else             { wr = -C1; wi =  S1; }
            float r = tr[a][c] * wr - ti[a][c] * wi;
            ti[a][c] = tr[a][c] * wi + ti[a][c] * wr;
            tr[a][c] = r;
        }
    }
#pragma unroll
    for (int c = 0; c < 4; ++c) {
        float s0r = tr[0][c] + tr[2][c], s0i = ti[0][c] + ti[2][c];
        float d0r = tr[0][c] - tr[2][c], d0i = ti[0][c] - ti[2][c];
        float s1r = tr[1][c] + tr[3][c], s1i = ti[1][c] + ti[3][c];
        float d1r = tr[1][c] - tr[3][c], d1i = ti[1][c] - ti[3][c];
        vr[c]      = s0r + s1r; vi[c]      = s0i + s1i;
        vr[c + 4]  = d0r + d1i; vi[c + 4]  = d0i - d1r;
        vr[c + 8]  = s0r - s1r; vi[c + 8]  = s0i - s1i;
        vr[c + 12] = d0r - d1i; vi[c + 12] = d0i + d1r;
    }
}

__device__ __forceinline__ void fft_stages01(float* vr, float* vi,
                                             float* SR, float* SI, int t) {
    dft16(vr, vi);
#pragma unroll
    for (int k = 0; k < 16; ++k) {
        int e = PADI(16 * t + k);
        SR[e] = vr[k]; SI[e] = vi[k];
    }
    __syncthreads();
#pragma unroll
    for (int m = 0; m < 16; ++m) {
        int e = PADI(t + 64 * m);
        vr[m] = SR[e]; vi[m] = SI[e];
    }
    int jm = t & 15;
#pragma unroll
    for (int m = 1; m < 16; ++m) {
        float2 w = g_tw[4 * m * jm];
        float r = vr[m] * w.x - vi[m] * w.y;
        vi[m] = vr[m] * w.y + vi[m] * w.x;
        vr[m] = r;
    }
    dft16(vr, vi);
    __syncthreads();
    int base1 = (t >> 4) * 256 + jm;
#pragma unroll
    for (int k = 0; k < 16; ++k) {
        int e = PADI(base1 + 16 * k);
        SR[e] = vr[k]; SI[e] = vi[k];
    }
    __syncthreads();
}

__device__ __forceinline__ void fft_stage2(const float* SR, const float* SI,
                                           int j, float* yr, float* yi) {
    float ar[4], ai[4];
#pragma unroll
    for (int m = 0; m < 4; ++m) {
        int e = PADI(j + 256 * m);
        ar[m] = SR[e]; ai[m] = SI[e];
    }
#pragma unroll
    for (int m = 1; m < 4; ++m) {
        float2 w = g_tw[m * j];
        float r = ar[m] * w.x - ai[m] * w.y;
        ai[m] = ar[m] * w.y + ai[m] * w.x;
        ar[m] = r;
    }
    float s0r = ar[0] + ar[2], s0i = ai[0] + ai[2];
    float d0r = ar[0] - ar[2], d0i = ai[0] - ai[2];
    float s1r = ar[1] + ar[3], s1i = ai[1] + ai[3];
    float d1r = ar[1] - ar[3], d1i = ai[1] - ai[3];
    yr[0] = s0r + s1r; yi[0] = s0i + s1i;
    yr[1] = d0r + d1i; yi[1] = d0i - d1r;
    yr[2] = s0r - s1r; yi[2] = s0i - s1i;
    yr[3] = d0r - d1i; yi[3] = d0i + d1r;
}

/* Two real rows packed per FFT; 2 FFTs per block; row-major coalesced output. */
__global__ void __launch_bounds__(128) row_fft_kernel(const float* __restrict__ x) {
    __shared__ float smr[2][FFT_SM], smi[2][FFT_SM];
    int f = threadIdx.x >> 6;
    int t = threadIdx.x & 63;
    int pr = blockIdx.x * 2 + f;
    float* SR = smr[f]; float* SI = smi[f];
    const float* rowA = x + (size_t)(2 * pr) * W;
    const float* rowB = rowA + W;
    float vr[16], vi[16];
#pragma unroll
    for (int m = 0; m < 16; ++m) {
        int idx = t + 64 * m;
        vr[m] = rowA[idx]; vi[m] = rowB[idx];
    }
    fft_stages01(vr, vi, SR, SI, t);
#pragma unroll
    for (int u = 0; u < 4; ++u) {
        int j = t + 64 * u;
        float yr[4], yi[4];
        fft_stage2(SR, SI, j, yr, yi);
#pragma unroll
        for (int k = 0; k < 4; ++k) {
            int e = PADI(j + 256 * k);
            SR[e] = yr[k]; SI[e] = yi[k];
        }
    }
    __syncthreads();
    float2* outA = g_bufA + (size_t)(2 * pr) * WR;
    float2* outB = outA + WR;
    for (int c = t; c < WR; c += 64) {
        int cn = (1024 - c) & 1023;
        float Zcr = SR[PADI(c)],  Zci = SI[PADI(c)];
        float Znr = SR[PADI(cn)], Zni = SI[PADI(cn)];
        float ar = 0.5f * (Zcr + Znr);
        float ai = 0.5f * (Zci - Zni);
        float dr = Zcr - Znr;
        float di = Zci + Zni;
        outA[c] = make_float2(ar, ai);
        outB[c] = make_float2(0.5f * di, -0.5f * dr);
    }
}

__global__ void transpose_kernel() {
    __shared__ float2 tile[32][33];
    int b  = blockIdx.z;
    int c0 = blockIdx.x * 32;
    int r0 = blockIdx.y * 32;
    int tx = threadIdx.x, ty = threadIdx.y;
    const float2* A = g_bufA + (size_t)b * H * WR;
    float2*       B = g_bufB + (size_t)b * WR * H;
#pragma unroll
    for (int i = ty; i < 32; i += 8) {
        int r = r0 + i, c = c0 + tx;
        if (c < WR) tile[i][tx] = A[(size_t)r * WR + c];
    }
    __syncthreads();
#pragma unroll
    for (int i = ty; i < 32; i += 8) {
        int c = c0 + i, r = r0 + tx;
        if (c < WR) B[(size_t)c * H + r] = tile[tx][i];
    }
}

/* 2 FFTs per block; epilogue: pu write, magnitude max, fused grad-y stats. */
__global__ void __launch_bounds__(128) col_fft_kernel() {
    __shared__ float smr[2][FFT_SM], smi[2][FFT_SM];
    __shared__ float sred[4], sgy[4], sgy2[4];
    int f = threadIdx.x >> 6;
    int t = threadIdx.x & 63;
    int blk = blockIdx.x * 2 + f;          /* b*WR + c */
    float* SR = smr[f]; float* SI = smi[f];
    const float2* in = g_bufB + (size_t)blk * H;
    float vr[16], vi[16];
#pragma unroll
    for (int m = 0; m < 16; ++m) {
        float2 z = in[t + 64 * m];
        vr[m] = z.x; vi[m] = z.y;
    }
    fft_stages01(vr, vi, SR, SI, t);

    float* pu = (float*)g_bufA;
    size_t outb = (size_t)blk * H;
    float maxm2 = 0.0f;
    float phv[16];
#pragma unroll
    for (int u = 0; u < 4; ++u) {
        int j = t + 64 * u;
        float yr[4], yi[4];
        fft_stage2(SR, SI, j, yr, yi);
#pragma unroll
        for (int k = 0; k < 4; ++k) {
            float m2 = fmaf(yr[k], yr[k], yi[k] * yi[k]);
            maxm2 = fmaxf(maxm2, m2);
            float ph = fast_phase(yi[k], yr[k]);
            phv[u + 4 * k] = ph;
            SR[PADI(j + 256 * k)] = ph;   /* in-place: thread-private slot set */
            pu[outb + j + 256 * k] = ph;
        }
    }
    __syncthreads();

    /* grad-y (along r) stats from smem phase column */
    float sy = 0.0f, sy2 = 0.0f;
#pragma unroll
    for (int s = 0; s < 16; ++s) {
        int r = t + 64 * s;
        float pc = phv[s];
        float gy;
        if (r == 0)          gy = SR[PADI(1)] - pc;
        else if (r == 1023)  gy = pc - SR[PADI(1022)];
        else                 gy = 0.5f * (SR[PADI(r + 1)] - SR[PADI(r - 1)]);
        sy += gy;
        sy2 = fmaf(gy, gy, sy2);
    }
#pragma unroll
    for (int o = 16; o; o >>= 1) {
        maxm2 = fmaxf(maxm2, __shfl_xor_sync(0xffffffffu, maxm2, o));
        sy  += __shfl_xor_sync(0xffffffffu, sy,  o);
        sy2 += __shfl_xor_sync(0xffffffffu, sy2, o);
    }
    int w = threadIdx.x >> 5;
    if ((threadIdx.x & 31) == 0) { sred[w] = maxm2; sgy[w] = sy; sgy2[w] = sy2; }
    __syncthreads();
    if (t == 0) {
        int b = blk / WR;
        float mm = fmaxf(sred[2 * f], sred[2 * f + 1]);
        atomicMax(&g_magmax[b], __float_as_int(sqrtf(mm)));
        atomicAdd(&g_stats[b * 4 + 1], (double)(sgy[2 * f] + sgy[2 * f + 1]));
        atomicAdd(&g_stats[b * 4 + 3], (double)(sgy2[2 * f] + sgy2[2 * f + 1]));
    }
}

/* grad-x only stats (gy fused into col_fft) */
__global__ void __launch_bounds__(256) statsx_kernel() {
    int b = blockIdx.y;
    const float4* pu4 = (const float4*)((const float*)g_bufA + (size_t)b * NPIX);
    float sx = 0.0f, sx2 = 0.0f;
    const int NQ = NPIX / 4;
    for (int q = blockIdx.x * 256 + threadIdx.x; q < NQ; q += gridDim.x * 256) {
        int c = q >> 8;
        float4 up, dn; float fac;
        if (c == 0)          { dn = pu4[q + 256]; up = pu4[q];       fac = 1.0f; }
        else if (c == WR - 1){ up = pu4[q - 256]; dn = pu4[q];       fac = 1.0f; }
        else                 { up = pu4[q - 256]; dn = pu4[q + 256]; fac = 0.5f; }
        float g0 = fac * (dn.x - up.x);
        float g1 = fac * (dn.y - up.y);
        float g2 = fac * (dn.z - up.z);
        float g3 = fac * (dn.w - up.w);
        sx += g0 + g1 + g2 + g3;
        sx2 = fmaf(g0, g0, fmaf(g1, g1, fmaf(g2, g2, fmaf(g3, g3, sx2))));
    }
    __shared__ double sbuf[8];
    double v2[2] = {(double)sx, (double)sx2};
#pragma unroll
    for (int qq = 0; qq < 2; ++qq) {
        double tt = v2[qq];
#pragma unroll
        for (int o = 16; o; o >>= 1) tt += __shfl_down_sync(0xffffffffu, tt, o);
        if ((threadIdx.x & 31) == 0) sbuf[threadIdx.x >> 5] = tt;
        __syncthreads();
        if (threadIdx.x < 8) {
            tt = sbuf[threadIdx.x];
#pragma unroll
            for (int o = 4; o; o >>= 1) tt += __shfl_down_sync(0xffu, tt, o);
            if (threadIdx.x == 0) atomicAdd(&g_stats[b * 4 + 2 * qq], tt);
        }
        __syncthreads();
    }
}

/* coeffs GEMM: 2x7 register blocking, KC=128, all threads compute Z then load pm */
#define KC 128
__global__ void __launch_bounds__(128) gemm_kernel() {
    __shared__ float pm_s[BATCH][KC + 4];
    __shared__ float z_s[TP][KC + 4];
    const float* pu = (const float*)g_bufA;
    int tid = threadIdx.x;
    int b0 = (tid >> 3) * 2;
    int t0 = (tid & 7) * 7;
    float acc[2][7];
#pragma unroll
    for (int a = 0; a < 2; ++a)
#pragma unroll
        for (int j = 0; j < 7; ++j) acc[a][j] = 0.0f;

    for (int k0 = blockIdx.x * KC; k0 < NPIX; k0 += gridDim.x * KC) {
        __syncthreads();
        {
            int pix = k0 + tid;
            int c = pix >> 10;
            int r = pix & 1023;
            float xg = (float)c * (1.0f / 256.0f) - 1.0f;
            float yg = (float)r * (2.0f / 1023.0f) - 1.0f;
            float rr = xg * xg + yg * yg;
            float rho = sqrtf(rr);
            float mk = (rho <= 1.0f) ? 1.0f : 0.0f;
            float inv = 1.0f / rho;
            float c1 = xg * inv, s1 = yg * inv;
            float q1 = rho, q2 = q1 * q1;
            float q3 = q2 * q1, q4 = q2 * q2, q5 = q3 * q2, q6 = q3 * q3;
            float q7 = q4 * q3, q8 = q4 * q4, q9 = q5 * q4;
            float c2 = c1 * c1 - s1 * s1, s2 = 2.0f * s1 * c1;
            float c3 = c1 * c2 - s1 * s2, s3 = s1 * c2 + c1 * s2;
            float c4 = c1 * c3 - s1 * s3, s4 = s1 * c3 + c1 * s3;
            float c5 = c1 * c4 - s1 * s4, s5 = s1 * c4 + c1 * s4;
            float c6 = c1 * c5 - s1 * s5, s6 = s1 * c5 + c1 * s5;
            float c7 = c1 * c6 - s1 * s6, s7 = s1 * c6 + c1 * s6;
            float c8 = c1 * c7 - s1 * s7, s8 = s1 * c7 + c1 * s7;
            float c9 = c1 * c8 - s1 * s8, s9 = s1 * c8 + c1 * s8;
#define ZST(tt, val) z_s[tt][tid] = (val) * mk
            ZST(0, 1.0f);
            ZST(1, q1 * s1);
            ZST(2, q1 * c1);
            ZST(3, q2 * s2);
            ZST(4, 2.0f * q2 - 1.0f);
            ZST(5, q2 * c2);
            ZST(6, q3 * s3);
            float R31 = 3.0f * q3 - 2.0f * q1;
            ZST(7, R31 * s1);
            ZST(8, R31 * c1);
            ZST(9, q3 * c3);
            ZST(10, q4 * s4);
            float R42 = 4.0f * q4 - 3.0f * q2;
            ZST(11, R42 * s2);
            ZST(12, 6.0f * q4 - 6.0f * q2 + 1.0f);
            ZST(13, R42 * c2);
            ZST(14, q4 * c4);
            ZST(15, q5 * s5);
            float R53 = 5.0f * q5 - 4.0f * q3;
            ZST(16, R53 * s3);
            float R51 = 10.0f * q5 - 12.0f * q3 + 3.0f * q1;
            ZST(17, R51 * s1);
            ZST(18, R51 * c1);
            ZST(19, R53 * c3);
            ZST(20, q5 * c5);
            ZST(21, q6 * s6);
            float R64 = 6.0f * q6 - 5.0f * q4;
            ZST(22, R64 * s4);
            float R62 = 15.0f * q6 - 20.0f * q4 + 6.0f * q2;
            ZST(23, R62 * s2);
            ZST(24, 20.0f * q6 - 30.0f * q4 + 12.0f * q2 - 1.0f);
            ZST(25, R62 * c2);
            ZST(26, R64 * c4);
            ZST(27, q6 * c6);
            ZST(28, q7 * s7);
            float R75 = 7.0f * q7 - 6.0f * q5;
            ZST(29, R75 * s5);
            float R73 = 21.0f * q7 - 30.0f * q5 + 10.0f * q3;
            ZST(30, R73 * s3);
            float R71 = 35.0f * q7 - 60.0f * q5 + 30.0f * q3 - 4.0f * q1;
            ZST(31, R71 * s1);
            ZST(32, R71 * c1);
            ZST(33, R73 * c3);
            ZST(34, R75 * c5);
            ZST(35, q7 * c7);
            ZST(36, q8 * s8);
            float R86 = 8.0f * q8 - 7.0f * q6;
            ZST(37, R86 * s6);
            float R84 = 28.0f * q8 - 42.0f * q6 + 15.0f * q4;
            ZST(38, R84 * s4);
            float R82 = 56.0f * q8 - 105.0f * q6 + 60.0f * q4 - 10.0f * q2;
            ZST(39, R82 * s2);
            ZST(40, 70.0f * q8 - 140.0f * q6 + 90.0f * q4 - 20.0f * q2 + 1.0f);
            ZST(41, R82 * c2);
            ZST(42, R84 * c4);
            ZST(43, R86 * c6);
            ZST(44, q8 * c8);
            ZST(45, q9 * s9);
            float R97 = 9.0f * q9 - 8.0f * q7;
            ZST(46, R97 * s7);
            float R95 = 36.0f * q9 - 56.0f * q7 + 21.0f * q5;
            ZST(47, R95 * s5);
            float R93 = 84.0f * q9 - 168.0f * q7 + 105.0f * q5 - 20.0f * q3;
            ZST(48, R93 * s3);
            float R91 = 126.0f * q9 - 280.0f * q7 + 210.0f * q5 - 60.0f * q3 + 5.0f * q1;
            ZST(49, R91 * s1);
            ZST(50, R91 * c1);
            ZST(51, R93 * c3);
            ZST(52, R95 * c5);
            ZST(53, R97 * c7);
            ZST(54, q9 * c9);
            z_s[55][tid] = 0.0f;
#undef ZST
            unsigned bal = __ballot_sync(0xffffffffu, mk > 0.5f);
            if ((tid & 31) == 0) atomicAdd(&g_maskcnt, __popc(bal));
        }
#pragma unroll
        for (int row = 0; row < BATCH; ++row)
            pm_s[row][tid] = pu[(size_t)row * NPIX + k0 + tid];
        __syncthreads();
#pragma unroll 8
        for (int kk = 0; kk < KC; kk += 4) {
            float4 a0 = *(const float4*)&pm_s[b0][kk];
            float4 a1 = *(const float4*)&pm_s[b0 + 1][kk];
#pragma unroll
            for (int j = 0; j < 7; ++j) {
                float4 zz = *(const float4*)&z_s[t0 + j][kk];
                acc[0][j] = fmaf(a0.x, zz.x, fmaf(a0.y, zz.y, fmaf(a0.z, zz.z, fmaf(a0.w, zz.w, acc[0][j]))));
                acc[1][j] = fmaf(a1.x, zz.x, fmaf(a1.y, zz.y, fmaf(a1.z, zz.z, fmaf(a1.w, zz.w, acc[1][j]))));
            }
        }
    }
#pragma unroll
    for (int j = 0; j < 7; ++j) {
        atomicAdd(&g_coeff[(b0)     * TP + t0 + j], acc[0][j]);
        atomicAdd(&g_coeff[(b0 + 1) * TP + t0 + j], acc[1][j]);
    }
}

__global__ void finalize_kernel(float* __restrict__ out) {
    int b = blockIdx.x;
    int j = threadIdx.x;
    if (j < 55) {
        out[b * 60 + j] = g_coeff[b * TP + j] / (float)g_maskcnt;
    } else if (j < 60) {
        double N = (double)NPIX;
        double sx = g_stats[b * 4 + 0], sy = g_stats[b * 4 + 1];
        double sx2 = g_stats[b * 4 + 2], sy2 = g_stats[b * 4 + 3];
        float v;
        if (j == 55)      v = (float)(sx / N);
        else if (j == 56) v = (float)(sy / N);
        else if (j == 57) v = (float)sqrt(fmax(0.0, (sx2 - sx * sx / N) / (N - 1.0)));
        else if (j == 58) v = (float)sqrt(fmax(0.0, (sy2 - sy * sy / N) / (N - 1.0)));
        else              v = __int_as_float(g_magmax[b]);
        out[b * 60 + j] = v;
    }
}

extern "C" void kernel_launch(void* const* d_in, const int* in_sizes, int n_in,
                              void* d_out, int out_size) {
    (void)in_sizes; (void)n_in; (void)out_size;
    const float* x = (const float*)d_in[0];
    float* out = (float*)d_out;

    init_kernel<<<1, 1024>>>();
    row_fft_kernel<<<BATCH * H / 4, 128>>>(x);
    transpose_kernel<<<dim3(17, H / 32, BATCH), dim3(32, 8)>>>();
    col_fft_kernel<<<BATCH * WR / 2, 128>>>();
    statsx_kernel<<<dim3(64, BATCH), 256>>>();
    gemm_kernel<<<592, 128>>>();
    finalize_kernel<<<BATCH, 64>>>(out);
}

// round 14
// speedup vs baseline: 1.4327x; 1.0906x over previous
#include <cuda_runtime.h>
#include <math.h>

#define BATCH 32
#define H 1024
#define W 1024
#define WR 513
#define NPIX (WR * H)
#define TP 56
#define TWO_PI 6.28318530717958647692f

#define PADI(e) ((e) + 5 * ((e) >> 5))
#define FFT_SM 1184

__device__ float2 g_bufA[(size_t)BATCH * H * WR];   /* row-fft out [b][r][c]; later pu [b][c][r] floats */
__device__ float2 g_bufB[(size_t)BATCH * WR * H];   /* transposed [b][c][r] */
__device__ float2 g_tw[1024];
__device__ float  g_coeff[BATCH * TP];
__device__ double g_stats[BATCH * 4];   /* sgx, sgy, sgx2, sgy2 */
__device__ int    g_magmax[BATCH];
__device__ int    g_maskcnt;

/* z_s row -> original term index (255 = pad) */
__device__ const unsigned char ROW2TERM[64] = {
    0,2,4,5,8,9,12,13,14,18,19,20,24,25,26,27,
    32,33,34,35,40,41,42,43,44,50,51,52,53,54,255,255,
    1,3,6,7,10,11,15,16,17,21,22,23,28,29,30,31,
    36,37,38,39,45,46,47,48,49,255,255,255,255,255,255,255
};

__global__ void init_kernel() {
    int t = threadIdx.x;   /* 1024 threads */
    float s, c;
    sincospif(-(float)t / 512.0f, &s, &c);
    g_tw[t] = make_float2(c, s);
    for (int i = t; i < BATCH * TP; i += 1024) g_coeff[i] = 0.0f;
    if (t < BATCH * 4) g_stats[t] = 0.0;
    if (t < BATCH)     g_magmax[t] = 0;
    if (t == 0)        g_maskcnt = 0;
}

/* atan2 -> [0, 2pi) unwrapped phase; minimax poly, max abs err ~1e-8 */
__device__ __forceinline__ float fast_phase(float y, float x) {
    float ax = fabsf(x), ay = fabsf(y);
    float mn = fminf(ax, ay), mx = fmaxf(ax, ay);
    float r = (mx == 0.0f) ? 0.0f : __fdividef(mn, mx);
    float a = r * r;
    float p = fmaf(a, -0.0040540580f, 0.0218612288f);
    p = fmaf(a, p, -0.0559098861f);
    p = fmaf(a, p, 0.0964200441f);
    p = fmaf(a, p, -0.1390853351f);
    p = fmaf(a, p, 0.1994653599f);
    p = fmaf(a, p, -0.3332985605f);
    p = fmaf(a, p, 0.9999993329f);
    float th = r * p;
    if (ay > ax)    th = 1.57079632679489662f - th;
    if (x < 0.0f)   th = 3.14159265358979324f - th;
    if (y < 0.0f)   th = TWO_PI - th;
    return th;
}

/* DFT-16 fully in registers. */
__device__ __forceinline__ void dft16(float* vr, float* vi) {
    const float C1 = 0.92387953251128675613f;
    const float S1 = 0.38268343236508977173f;
    const float C2 = 0.70710678118654752440f;
    float tr[4][4], ti[4][4];
#pragma unroll
    for (int a = 0; a < 4; ++a) {
        float x0r = vr[a],      x0i = vi[a];
        float x1r = vr[a + 4],  x1i = vi[a + 4];
        float x2r = vr[a + 8],  x2i = vi[a + 8];
        float x3r = vr[a + 12], x3i = vi[a + 12];
        float s0r = x0r + x2r, s0i = x0i + x2i;
        float d0r = x0r - x2r, d0i = x0i - x2i;
        float s1r = x1r + x3r, s1i = x1i + x3i;
        float d1r = x1r - x3r, d1i = x1i - x3i;
        tr[a][0] = s0r + s1r; ti[a][0] = s0i + s1i;
        tr[a][1] = d0r + d1i; ti[a][1] = d0i - d1r;
        tr[a][2] = s0r - s1r; ti[a][2] = s0i - s1i;
        tr[a][3] = d0r - d1i; ti[a][3] = d0i + d1r;
    }
#pragma unroll
    for (int a = 1; a < 4; ++a) {
#pragma unroll
        for (int c = 1; c < 4; ++c) {
            int k = a * c;
            float wr, wi;
            if (k == 1)      { wr =  C1; wi = -S1; }
            else if (k == 2) { wr =  C2; wi = -C2; }
            else if (k == 3) { wr =  S1; wi = -C1; }
            else if (k == 4) { wr = 0.f; wi = -1.f; }
            else if (k == 6) { wr = -C2; wi = -C2; }
            else             { wr = -C1; wi =  S1; }
            float r = tr[a][c] * wr - ti[a][c] * wi;
            ti[a][c] = tr[a][c] * wi + ti[a][c] * wr;
            tr[a][c] = r;
        }
    }
#pragma unroll
    for (int c = 0; c < 4; ++c) {
        float s0r = tr[0][c] + tr[2][c], s0i = ti[0][c] + ti[2][c];
        float d0r = tr[0][c] - tr[2][c], d0i = ti[0][c] - ti[2][c];
        float s1r = tr[1][c] + tr[3][c], s1i = ti[1][c] + ti[3][c];
        float d1r = tr[1][c] - tr[3][c], d1i = ti[1][c] - ti[3][c];
        vr[c]      = s0r + s1r; vi[c]      = s0i + s1i;
        vr[c + 4]  = d0r + d1i; vi[c + 4]  = d0i - d1r;
        vr[c + 8]  = s0r - s1r; vi[c + 8]  = s0i - s1i;
        vr[c + 12] = d0r - d1i; vi[c + 12] = d0i + d1r;
    }
}

__device__ __forceinline__ void fft_stages01(float* vr, float* vi,
                                             float* SR, float* SI, int t) {
    dft16(vr, vi);
#pragma unroll
    for (int k = 0; k < 16; ++k) {
        int e = PADI(16 * t + k);
        SR[e] = vr[k]; SI[e] = vi[k];
    }
    __syncthreads();
#pragma unroll
    for (int m = 0; m < 16; ++m) {
        int e = PADI(t + 64 * m);
        vr[m] = SR[e]; vi[m] = SI[e];
    }
    int jm = t & 15;
#pragma unroll
    for (int m = 1; m < 16; ++m) {
        float2 w = g_tw[4 * m * jm];
        float r = vr[m] * w.x - vi[m] * w.y;
        vi[m] = vr[m] * w.y + vi[m] * w.x;
        vr[m] = r;
    }
    dft16(vr, vi);
    __syncthreads();
    int base1 = (t >> 4) * 256 + jm;
#pragma unroll
    for (int k = 0; k < 16; ++k) {
        int e = PADI(base1 + 16 * k);
        SR[e] = vr[k]; SI[e] = vi[k];
    }
    __syncthreads();
}

__device__ __forceinline__ void fft_stage2(const float* SR, const float* SI,
                                           int j, float* yr, float* yi) {
    float ar[4], ai[4];
#pragma unroll
    for (int m = 0; m < 4; ++m) {
        int e = PADI(j + 256 * m);
        ar[m] = SR[e]; ai[m] = SI[e];
    }
#pragma unroll
    for (int m = 1; m < 4; ++m) {
        float2 w = g_tw[m * j];
        float r = ar[m] * w.x - ai[m] * w.y;
        ai[m] = ar[m] * w.y + ai[m] * w.x;
        ar[m] = r;
    }
    float s0r = ar[0] + ar[2], s0i = ai[0] + ai[2];
    float d0r = ar[0] - ar[2], d0i = ai[0] - ai[2];
    float s1r = ar[1] + ar[3], s1i = ai[1] + ai[3];
    float d1r = ar[1] - ar[3], d1i = ai[1] - ai[3];
    yr[0] = s0r + s1r; yi[0] = s0i + s1i;
    yr[1] = d0r + d1i; yi[1] = d0i - d1r;
    yr[2] = s0r - s1r; yi[2] = s0i - s1i;
    yr[3] = d0r - d1i; yi[3] = d0i + d1r;
}

/* Two real rows packed per FFT; 2 FFTs per block; row-major coalesced output. */
__global__ void __launch_bounds__(128) row_fft_kernel(const float* __restrict__ x) {
    __shared__ float smr[2][FFT_SM], smi[2][FFT_SM];
    int f = threadIdx.x >> 6;
    int t = threadIdx.x & 63;
    int pr = blockIdx.x * 2 + f;
    float* SR = smr[f]; float* SI = smi[f];
    const float* rowA = x + (size_t)(2 * pr) * W;
    const float* rowB = rowA + W;
    float vr[16], vi[16];
#pragma unroll
    for (int m = 0; m < 16; ++m) {
        int idx = t + 64 * m;
        vr[m] = rowA[idx]; vi[m] = rowB[idx];
    }
    fft_stages01(vr, vi, SR, SI, t);
#pragma unroll
    for (int u = 0; u < 4; ++u) {
        int j = t + 64 * u;
        float yr[4], yi[4];
        fft_stage2(SR, SI, j, yr, yi);
#pragma unroll
        for (int k = 0; k < 4; ++k) {
            int e = PADI(j + 256 * k);
            SR[e] = yr[k]; SI[e] = yi[k];
        }
    }
    __syncthreads();
    float2* outA = g_bufA + (size_t)(2 * pr) * WR;
    float2* outB = outA + WR;
    for (int c = t; c < WR; c += 64) {
        int cn = (1024 - c) & 1023;
        float Zcr = SR[PADI(c)],  Zci = SI[PADI(c)];
        float Znr = SR[PADI(cn)], Zni = SI[PADI(cn)];
        float ar = 0.5f * (Zcr + Znr);
        float ai = 0.5f * (Zci - Zni);
        float dr = Zcr - Znr;
        float di = Zci + Zni;
        outA[c] = make_float2(ar, ai);
        outB[c] = make_float2(0.5f * di, -0.5f * dr);
    }
}

__global__ void transpose_kernel() {
    __shared__ float2 tile[32][33];
    int b  = blockIdx.z;
    int c0 = blockIdx.x * 32;
    int r0 = blockIdx.y * 32;
    int tx = threadIdx.x, ty = threadIdx.y;
    const float2* A = g_bufA + (size_t)b * H * WR;
    float2*       B = g_bufB + (size_t)b * WR * H;
#pragma unroll
    for (int i = ty; i < 32; i += 8) {
        int r = r0 + i, c = c0 + tx;
        if (c < WR) tile[i][tx] = A[(size_t)r * WR + c];
    }
    __syncthreads();
#pragma unroll
    for (int i = ty; i < 32; i += 8) {
        int c = c0 + i, r = r0 + tx;
        if (c < WR) B[(size_t)c * H + r] = tile[tx][i];
    }
}

/* 2 FFTs per block; epilogue: pu write, magnitude max, fused grad-y stats. */
__global__ void __launch_bounds__(128) col_fft_kernel() {
    __shared__ float smr[2][FFT_SM], smi[2][FFT_SM];
    __shared__ float sred[4], sgy[4], sgy2[4];
    int f = threadIdx.x >> 6;
    int t = threadIdx.x & 63;
    int blk = blockIdx.x * 2 + f;          /* b*WR + c */
    float* SR = smr[f]; float* SI = smi[f];
    const float2* in = g_bufB + (size_t)blk * H;
    float vr[16], vi[16];
#pragma unroll
    for (int m = 0; m < 16; ++m) {
        float2 z = in[t + 64 * m];
        vr[m] = z.x; vi[m] = z.y;
    }
    fft_stages01(vr, vi, SR, SI, t);

    float* pu = (float*)g_bufA;
    size_t outb = (size_t)blk * H;
    float maxm2 = 0.0f;
    float phv[16];
#pragma unroll
    for (int u = 0; u < 4; ++u) {
        int j = t + 64 * u;
        float yr[4], yi[4];
        fft_stage2(SR, SI, j, yr, yi);
#pragma unroll
        for (int k = 0; k < 4; ++k) {
            float m2 = fmaf(yr[k], yr[k], yi[k] * yi[k]);
            maxm2 = fmaxf(maxm2, m2);
            float ph = fast_phase(yi[k], yr[k]);
            phv[u + 4 * k] = ph;
            SR[PADI(j + 256 * k)] = ph;   /* in-place: thread-private slot set */
            pu[outb + j + 256 * k] = ph;
        }
    }
    __syncthreads();

    /* grad-y (along r) stats from smem phase column */
    float sy = 0.0f, sy2 = 0.0f;
#pragma unroll
    for (int s = 0; s < 16; ++s) {
        int r = t + 64 * s;
        float pc = phv[s];
        float gy;
        if (r == 0)          gy = SR[PADI(1)] - pc;
        else if (r == 1023)  gy = pc - SR[PADI(1022)];
        else                 gy = 0.5f * (SR[PADI(r + 1)] - SR[PADI(r - 1)]);
        sy += gy;
        sy2 = fmaf(gy, gy, sy2);
    }
#pragma unroll
    for (int o = 16; o; o >>= 1) {
        maxm2 = fmaxf(maxm2, __shfl_xor_sync(0xffffffffu, maxm2, o));
        sy  += __shfl_xor_sync(0xffffffffu, sy,  o);
        sy2 += __shfl_xor_sync(0xffffffffu, sy2, o);
    }
    int w = threadIdx.x >> 5;
    if ((threadIdx.x & 31) == 0) { sred[w] = maxm2; sgy[w] = sy; sgy2[w] = sy2; }
    __syncthreads();
    if (t == 0) {
        int b = blk / WR;
        float mm = fmaxf(sred[2 * f], sred[2 * f + 1]);
        atomicMax(&g_magmax[b], __float_as_int(sqrtf(mm)));
        atomicAdd(&g_stats[b * 4 + 1], (double)(sgy[2 * f] + sgy[2 * f + 1]));
        atomicAdd(&g_stats[b * 4 + 3], (double)(sgy2[2 * f] + sgy2[2 * f + 1]));
    }
}

/* grad-x only stats (gy fused into col_fft) */
__global__ void __launch_bounds__(256) statsx_kernel() {
    int b = blockIdx.y;
    const float4* pu4 = (const float4*)((const float*)g_bufA + (size_t)b * NPIX);
    float sx = 0.0f, sx2 = 0.0f;
    const int NQ = NPIX / 4;
    for (int q = blockIdx.x * 256 + threadIdx.x; q < NQ; q += gridDim.x * 256) {
        int c = q >> 8;
        float4 up, dn; float fac;
        if (c == 0)          { dn = pu4[q + 256]; up = pu4[q];       fac = 1.0f; }
        else if (c == WR - 1){ up = pu4[q - 256]; dn = pu4[q];       fac = 1.0f; }
        else                 { up = pu4[q - 256]; dn = pu4[q + 256]; fac = 0.5f; }
        float g0 = fac * (dn.x - up.x);
        float g1 = fac * (dn.y - up.y);
        float g2 = fac * (dn.z - up.z);
        float g3 = fac * (dn.w - up.w);
        sx += g0 + g1 + g2 + g3;
        sx2 = fmaf(g0, g0, fmaf(g1, g1, fmaf(g2, g2, fmaf(g3, g3, sx2))));
    }
    __shared__ double sbuf[8];
    double v2[2] = {(double)sx, (double)sx2};
#pragma unroll
    for (int qq = 0; qq < 2; ++qq) {
        double tt = v2[qq];
#pragma unroll
        for (int o = 16; o; o >>= 1) tt += __shfl_down_sync(0xffffffffu, tt, o);
        if ((threadIdx.x & 31) == 0) sbuf[threadIdx.x >> 5] = tt;
        __syncthreads();
        if (threadIdx.x < 8) {
            tt = sbuf[threadIdx.x];
#pragma unroll
            for (int o = 4; o; o >>= 1) tt += __shfl_down_sync(0xffu, tt, o);
            if (threadIdx.x == 0) atomicAdd(&g_stats[b * 4 + 2 * qq], tt);
        }
        __syncthreads();
    }
}

/* coeffs GEMM with y-reflection symmetry: K halved.
   pm_s rows 0..31 = pu(r)+pu(1023-r) per batch, rows 32..63 = difference.
   z_s rows 0..29 even (cos) terms, 32..56 odd (sin) terms, rest zero.
   Thread = (bg, tg): 2 batches x 8 term-rows (row = 8*jj + tg). */
#define KC 128
#define KHALF (WR * 512)
__global__ void __launch_bounds__(128) gemm_kernel() {
    __shared__ float pm_s[64][KC + 4];
    __shared__ float z_s[64][KC + 4];
    const float* pu = (const float*)g_bufA;
    int tid = threadIdx.x;
    int bg = tid >> 3;      /* 0..15 */
    int tg = tid & 7;       /* 0..7  */
    int b0 = 2 * bg;
    float acc[8][2];
#pragma unroll
    for (int jj = 0; jj < 8; ++jj) { acc[jj][0] = 0.0f; acc[jj][1] = 0.0f; }

    for (int k0 = blockIdx.x * KC; k0 < KHALF; k0 += gridDim.x * KC) {
        int c  = k0 >> 9;       /* chunk lies inside one column: 128 | 512 */
        int r0 = k0 & 511;
        int rh = r0 + tid;
        __syncthreads();
        /* fold batch maps: psum/pdiff (mirror read contiguous descending) */
#pragma unroll 4
        for (int row = 0; row < 32; ++row) {
            const float* base = pu + ((size_t)row * WR + c) * 1024;
            float fv = base[rh];
            float mv = base[1023 - rh];
            pm_s[row][tid]      = fv + mv;
            pm_s[row + 32][tid] = fv - mv;
        }
        /* Zernike basis at (c, rh), parity-sorted rows */
        {
            float xg = (float)c * (1.0f / 256.0f) - 1.0f;
            float yg = (float)rh * (2.0f / 1023.0f) - 1.0f;
            float rr = xg * xg + yg * yg;
            float rho = sqrtf(rr);
            float mk = (rho <= 1.0f) ? 1.0f : 0.0f;
            float inv = 1.0f / rho;
            float c1 = xg * inv, s1 = yg * inv;
            float q1 = rho, q2 = q1 * q1;
            float q3 = q2 * q1, q4 = q2 * q2, q5 = q3 * q2, q6 = q3 * q3;
            float q7 = q4 * q3, q8 = q4 * q4, q9 = q5 * q4;
            float c2 = c1 * c1 - s1 * s1, s2 = 2.0f * s1 * c1;
            float c3 = c1 * c2 - s1 * s2, s3 = s1 * c2 + c1 * s2;
            float c4 = c1 * c3 - s1 * s3, s4 = s1 * c3 + c1 * s3;
            float c5 = c1 * c4 - s1 * s4, s5 = s1 * c4 + c1 * s4;
            float c6 = c1 * c5 - s1 * s5, s6 = s1 * c5 + c1 * s5;
            float c7 = c1 * c6 - s1 * s6, s7 = s1 * c6 + c1 * s6;
            float c8 = c1 * c7 - s1 * s7, s8 = s1 * c7 + c1 * s7;
            float c9 = c1 * c8 - s1 * s8, s9 = s1 * c8 + c1 * s8;
            float R31 = 3.0f * q3 - 2.0f * q1;
            float R42 = 4.0f * q4 - 3.0f * q2;
            float R53 = 5.0f * q5 - 4.0f * q3;
            float R51 = 10.0f * q5 - 12.0f * q3 + 3.0f * q1;
            float R64 = 6.0f * q6 - 5.0f * q4;
            float R62 = 15.0f * q6 - 20.0f * q4 + 6.0f * q2;
            float R75 = 7.0f * q7 - 6.0f * q5;
            float R73 = 21.0f * q7 - 30.0f * q5 + 10.0f * q3;
            float R71 = 35.0f * q7 - 60.0f * q5 + 30.0f * q3 - 4.0f * q1;
            float R86 = 8.0f * q8 - 7.0f * q6;
            float R84 = 28.0f * q8 - 42.0f * q6 + 15.0f * q4;
            float R82 = 56.0f * q8 - 105.0f * q6 + 60.0f * q4 - 10.0f * q2;
            float R97 = 9.0f * q9 - 8.0f * q7;
            float R95 = 36.0f * q9 - 56.0f * q7 + 21.0f * q5;
            float R93 = 84.0f * q9 - 168.0f * q7 + 105.0f * q5 - 20.0f * q3;
            float R91 = 126.0f * q9 - 280.0f * q7 + 210.0f * q5 - 60.0f * q3 + 5.0f * q1;
#define ZROW(rw, val) z_s[rw][tid] = (val) * mk
            /* even (cos) terms -> rows 0..29 */
            ZROW(0, 1.0f);
            ZROW(1, q1 * c1);
            ZROW(2, 2.0f * q2 - 1.0f);
            ZROW(3, q2 * c2);
            ZROW(4, R31 * c1);
            ZROW(5, q3 * c3);
            ZROW(6, 6.0f * q4 - 6.0f * q2 + 1.0f);
            ZROW(7, R42 * c2);
            ZROW(8, q4 * c4);
            ZROW(9, R51 * c1);
            ZROW(10, R53 * c3);
            ZROW(11, q5 * c5);
            ZROW(12, 20.0f * q6 - 30.0f * q4 + 12.0f * q2 - 1.0f);
            ZROW(13, R62 * c2);
            ZROW(14, R64 * c4);
            ZROW(15, q6 * c6);
            ZROW(16, R71 * c1);
            ZROW(17, R73 * c3);
            ZROW(18, R75 * c5);
            ZROW(19, q7 * c7);
            ZROW(20, 70.0f * q8 - 140.0f * q6 + 90.0f * q4 - 20.0f * q2 + 1.0f);
            ZROW(21, R82 * c2);
            ZROW(22, R84 * c4);
            ZROW(23, R86 * c6);
            ZROW(24, q8 * c8);
            ZROW(25, R91 * c1);
            ZROW(26, R93 * c3);
            ZROW(27, R95 * c5);
            ZROW(28, R97 * c7);
            ZROW(29, q9 * c9);
            z_s[30][tid] = 0.0f;
            z_s[31][tid] = 0.0f;
            /* odd (sin) terms -> rows 32..56 */
            ZROW(32, q1 * s1);
            ZROW(33, q2 * s2);
            ZROW(34, q3 * s3);
            ZROW(35, R31 * s1);
            ZROW(36, q4 * s4);
            ZROW(37, R42 * s2);
            ZROW(38, q5 * s5);
            ZROW(39, R53 * s3);
            ZROW(40, R51 * s1);
            ZROW(41, q6 * s6);
            ZROW(42, R64 * s4);
            ZROW(43, R62 * s2);
            ZROW(44, q7 * s7);
            ZROW(45, R75 * s5);
            ZROW(46, R73 * s3);
            ZROW(47, R71 * s1);
            ZROW(48, q8 * s8);
            ZROW(49, R86 * s6);
            ZROW(50, R84 * s4);
            ZROW(51, R82 * s2);
            ZROW(52, q9 * s9);
            ZROW(53, R97 * s7);
            ZROW(54, R95 * s5);
            ZROW(55, R93 * s3);
            ZROW(56, R91 * s1);
#pragma unroll
            for (int rw = 57; rw < 64; ++rw) z_s[rw][tid] = 0.0f;
#undef ZROW
            unsigned bal = __ballot_sync(0xffffffffu, mk > 0.5f);
            if ((tid & 31) == 0) atomicAdd(&g_maskcnt, 2 * __popc(bal));
        }
        __syncthreads();
#pragma unroll 4
        for (int kk = 0; kk < KC; kk += 4) {
            float4 ps0 = *(const float4*)&pm_s[b0][kk];
            float4 ps1 = *(const float4*)&pm_s[b0 + 1][kk];
            float4 pd0 = *(const float4*)&pm_s[b0 + 32][kk];
            float4 pd1 = *(const float4*)&pm_s[b0 + 33][kk];
#pragma unroll
            for (int jj = 0; jj < 4; ++jj) {          /* even rows */
                float4 zz = *(const float4*)&z_s[8 * jj + tg][kk];
                acc[jj][0] = fmaf(ps0.x, zz.x, fmaf(ps0.y, zz.y, fmaf(ps0.z, zz.z, fmaf(ps0.w, zz.w, acc[jj][0]))));
                acc[jj][1] = fmaf(ps1.x, zz.x, fmaf(ps1.y, zz.y, fmaf(ps1.z, zz.z, fmaf(ps1.w, zz.w, acc[jj][1]))));
            }
#pragma unroll
            for (int jj = 4; jj < 8; ++jj) {          /* odd rows */
                float4 zz = *(const float4*)&z_s[8 * jj + tg][kk];
                acc[jj][0] = fmaf(pd0.x, zz.x, fmaf(pd0.y, zz.y, fmaf(pd0.z, zz.z, fmaf(pd0.w, zz.w, acc[jj][0]))));
                acc[jj][1] = fmaf(pd1.x, zz.x, fmaf(pd1.y, zz.y, fmaf(pd1.z, zz.z, fmaf(pd1.w, zz.w, acc[jj][1]))));
            }
        }
    }
#pragma unroll
    for (int jj = 0; jj < 8; ++jj) {
        int rw = 8 * jj + tg;
        int tm = ROW2TERM[rw];
        if (tm != 255) {
            atomicAdd(&g_coeff[b0 * TP + tm], acc[jj][0]);
            atomicAdd(&g_coeff[(b0 + 1) * TP + tm], acc[jj][1]);
        }
    }
}

__global__ void finalize_kernel(float* __restrict__ out) {
    int b = blockIdx.x;
    int j = threadIdx.x;
    if (j < 55) {
        out[b * 60 + j] = g_coeff[b * TP + j] / (float)g_maskcnt;
    } else if (j < 60) {
        double N = (double)NPIX;
        double sx = g_stats[b * 4 + 0], sy = g_stats[b * 4 + 1];
        double sx2 = g_stats[b * 4 + 2], sy2 = g_stats[b * 4 + 3];
        float v;
        if (j == 55)      v = (float)(sx / N);
        else if (j == 56) v = (float)(sy / N);
        else if (j == 57) v = (float)sqrt(fmax(0.0, (sx2 - sx * sx / N) / (N - 1.0)));
        else if (j == 58) v = (float)sqrt(fmax(0.0, (sy2 - sy * sy / N) / (N - 1.0)));
        else              v = __int_as_float(g_magmax[b]);
        out[b * 60 + j] = v;
    }
}

extern "C" void kernel_launch(void* const* d_in, const int* in_sizes, int n_in,
                              void* d_out, int out_size) {
    (void)in_sizes; (void)n_in; (void)out_size;
    const float* x = (const float*)d_in[0];
    float* out = (float*)d_out;

    init_kernel<<<1, 1024>>>();
    row_fft_kernel<<<BATCH * H / 4, 128>>>(x);
    transpose_kernel<<<dim3(17, H / 32, BATCH), dim3(32, 8)>>>();
    col_fft_kernel<<<BATCH * WR / 2, 128>>>();
    statsx_kernel<<<dim3(64, BATCH), 256>>>();
    gemm_kernel<<<684, 128>>>();
    finalize_kernel<<<BATCH, 64>>>(out);
}

// round 15
// speedup vs baseline: 1.5486x; 1.0809x over previous
#include <cuda_runtime.h>
#include <math.h>

#define BATCH 32
#define H 1024
#define W 1024
#define WR 513
#define NPIX (WR * H)
#define TP 56
#define TWO_PI 6.28318530717958647692f

#define PADI(e) ((e) + 5 * ((e) >> 5))
#define FFT_SM 1184
#define COL_SM 1192
#define CT 17   /* column tiles of 32 */

__device__ float2 g_bufA[(size_t)BATCH * H * WR];            /* pu [b][c][r] floats */
__device__ float2 g_bufB[(size_t)BATCH * CT * 1024 * 32];    /* spectra, blocked [b][ct][r][cw] */
__device__ float2 g_tw[1024];
__device__ float  g_coeff[BATCH * TP];
__device__ double g_stats[BATCH * 4];   /* sgx, sgy, sgx2, sgy2 */
__device__ int    g_magmax[BATCH];
__device__ int    g_maskcnt;

/* z_s row -> original term index (255 = pad) */
__device__ const unsigned char ROW2TERM[64] = {
    0,2,4,5,8,9,12,13,14,18,19,20,24,25,26,27,
    32,33,34,35,40,41,42,43,44,50,51,52,53,54,255,255,
    1,3,6,7,10,11,15,16,17,21,22,23,28,29,30,31,
    36,37,38,39,45,46,47,48,49,255,255,255,255,255,255,255
};

__global__ void init_kernel() {
    int t = threadIdx.x;   /* 1024 threads */
    float s, c;
    sincospif(-(float)t / 512.0f, &s, &c);
    g_tw[t] = make_float2(c, s);
    for (int i = t; i < BATCH * TP; i += 1024) g_coeff[i] = 0.0f;
    if (t < BATCH * 4) g_stats[t] = 0.0;
    if (t < BATCH)     g_magmax[t] = 0;
    if (t == 0)        g_maskcnt = 0;
}

/* atan2 -> [0, 2pi) unwrapped phase; minimax poly, max abs err ~1e-8 */
__device__ __forceinline__ float fast_phase(float y, float x) {
    float ax = fabsf(x), ay = fabsf(y);
    float mn = fminf(ax, ay), mx = fmaxf(ax, ay);
    float r = (mx == 0.0f) ? 0.0f : __fdividef(mn, mx);
    float a = r * r;
    float p = fmaf(a, -0.0040540580f, 0.0218612288f);
    p = fmaf(a, p, -0.0559098861f);
    p = fmaf(a, p, 0.0964200441f);
    p = fmaf(a, p, -0.1390853351f);
    p = fmaf(a, p, 0.1994653599f);
    p = fmaf(a, p, -0.3332985605f);
    p = fmaf(a, p, 0.9999993329f);
    float th = r * p;
    if (ay > ax)    th = 1.57079632679489662f - th;
    if (x < 0.0f)   th = 3.14159265358979324f - th;
    if (y < 0.0f)   th = TWO_PI - th;
    return th;
}

/* DFT-16 fully in registers. */
__device__ __forceinline__ void dft16(float* vr, float* vi) {
    const float C1 = 0.92387953251128675613f;
    const float S1 = 0.38268343236508977173f;
    const float C2 = 0.70710678118654752440f;
    float tr[4][4], ti[4][4];
#pragma unroll
    for (int a = 0; a < 4; ++a) {
        float x0r = vr[a],      x0i = vi[a];
        float x1r = vr[a + 4],  x1i = vi[a + 4];
        float x2r = vr[a + 8],  x2i = vi[a + 8];
        float x3r = vr[a + 12], x3i = vi[a + 12];
        float s0r = x0r + x2r, s0i = x0i + x2i;
        float d0r = x0r - x2r, d0i = x0i - x2i;
        float s1r = x1r + x3r, s1i = x1i + x3i;
        float d1r = x1r - x3r, d1i = x1i - x3i;
        tr[a][0] = s0r + s1r; ti[a][0] = s0i + s1i;
        tr[a][1] = d0r + d1i; ti[a][1] = d0i - d1r;
        tr[a][2] = s0r - s1r; ti[a][2] = s0i - s1i;
        tr[a][3] = d0r - d1i; ti[a][3] = d0i + d1r;
    }
#pragma unroll
    for (int a = 1; a < 4; ++a) {
#pragma unroll
        for (int c = 1; c < 4; ++c) {
            int k = a * c;
            float wr, wi;
            if (k == 1)      { wr =  C1; wi = -S1; }
            else if (k == 2) { wr =  C2; wi = -C2; }
            else if (k == 3) { wr =  S1; wi = -C1; }
            else if (k == 4) { wr = 0.f; wi = -1.f; }
            else if (k == 6) { wr = -C2; wi = -C2; }
            else             { wr = -C1; wi =  S1; }
            float r = tr[a][c] * wr - ti[a][c] * wi;
            ti[a][c] = tr[a][c] * wi + ti[a][c] * wr;
            tr[a][c] = r;
        }
    }
#pragma unroll
    for (int c = 0; c < 4; ++c) {
        float s0r = tr[0][c] + tr[2][c], s0i = ti[0][c] + ti[2][c];
        float d0r = tr[0][c] - tr[2][c], d0i = ti[0][c] - ti[2][c];
        float s1r = tr[1][c] + tr[3][c], s1i = ti[1][c] + ti[3][c];
        float d1r = tr[1][c] - tr[3][c], d1i = ti[1][c] - ti[3][c];
        vr[c]      = s0r + s1r; vi[c]      = s0i + s1i;
        vr[c + 4]  = d0r + d1i; vi[c + 4]  = d0i - d1r;
        vr[c + 8]  = s0r - s1r; vi[c + 8]  = s0i - s1i;
        vr[c + 12] = d0r - d1i; vi[c + 12] = d0i + d1r;
    }
}

__device__ __forceinline__ void fft_stages01(float* vr, float* vi,
                                             float* SR, float* SI, int t) {
    dft16(vr, vi);
#pragma unroll
    for (int k = 0; k < 16; ++k) {
        int e = PADI(16 * t + k);
        SR[e] = vr[k]; SI[e] = vi[k];
    }
    __syncthreads();
#pragma unroll
    for (int m = 0; m < 16; ++m) {
        int e = PADI(t + 64 * m);
        vr[m] = SR[e]; vi[m] = SI[e];
    }
    int jm = t & 15;
#pragma unroll
    for (int m = 1; m < 16; ++m) {
        float2 w = g_tw[4 * m * jm];
        float r = vr[m] * w.x - vi[m] * w.y;
        vi[m] = vr[m] * w.y + vi[m] * w.x;
        vr[m] = r;
    }
    dft16(vr, vi);
    __syncthreads();
    int base1 = (t >> 4) * 256 + jm;
#pragma unroll
    for (int k = 0; k < 16; ++k) {
        int e = PADI(base1 + 16 * k);
        SR[e] = vr[k]; SI[e] = vi[k];
    }
    __syncthreads();
}

__device__ __forceinline__ void fft_stage2(const float* SR, const float* SI,
                                           int j, float* yr, float* yi) {
    float ar[4], ai[4];
#pragma unroll
    for (int m = 0; m < 4; ++m) {
        int e = PADI(j + 256 * m);
        ar[m] = SR[e]; ai[m] = SI[e];
    }
#pragma unroll
    for (int m = 1; m < 4; ++m) {
        float2 w = g_tw[m * j];
        float r = ar[m] * w.x - ai[m] * w.y;
        ai[m] = ar[m] * w.y + ai[m] * w.x;
        ar[m] = r;
    }
    float s0r = ar[0] + ar[2], s0i = ai[0] + ai[2];
    float d0r = ar[0] - ar[2], d0i = ai[0] - ai[2];
    float s1r = ar[1] + ar[3], s1i = ai[1] + ai[3];
    float d1r = ar[1] - ar[3], d1i = ai[1] - ai[3];
    yr[0] = s0r + s1r; yi[0] = s0i + s1i;
    yr[1] = d0r + d1i; yi[1] = d0i - d1r;
    yr[2] = s0r - s1r; yi[2] = s0i - s1i;
    yr[3] = d0r - d1i; yi[3] = d0i + d1r;
}

/* Two real rows packed per FFT; 2 FFTs per block.
   Output written to blocked layout [b][ct][r][cw] (256B/warp segments). */
__global__ void __launch_bounds__(128) row_fft_kernel(const float* __restrict__ x) {
    __shared__ float smr[2][FFT_SM], smi[2][FFT_SM];
    int f = threadIdx.x >> 6;
    int t = threadIdx.x & 63;
    int pr = blockIdx.x * 2 + f;
    float* SR = smr[f]; float* SI = smi[f];
    const float* rowA = x + (size_t)(2 * pr) * W;
    const float* rowB = rowA + W;
    float vr[16], vi[16];
#pragma unroll
    for (int m = 0; m < 16; ++m) {
        int idx = t + 64 * m;
        vr[m] = rowA[idx]; vi[m] = rowB[idx];
    }
    fft_stages01(vr, vi, SR, SI, t);
#pragma unroll
    for (int u = 0; u < 4; ++u) {
        int j = t + 64 * u;
        float yr[4], yi[4];
        fft_stage2(SR, SI, j, yr, yi);
#pragma unroll
        for (int k = 0; k < 4; ++k) {
            int e = PADI(j + 256 * k);
            SR[e] = yr[k]; SI[e] = yi[k];
        }
    }
    __syncthreads();
    int rowidx = 2 * pr;
    int b  = rowidx >> 10;
    int rA = rowidx & 1023;
    for (int c = t; c < WR; c += 64) {
        int cn = (1024 - c) & 1023;
        float Zcr = SR[PADI(c)],  Zci = SI[PADI(c)];
        float Znr = SR[PADI(cn)], Zni = SI[PADI(cn)];
        float ar = 0.5f * (Zcr + Znr);
        float ai = 0.5f * (Zci - Zni);
        float dr = Zcr - Znr;
        float di = Zci + Zni;
        size_t idx = ((((size_t)b * CT + (c >> 5)) * 1024 + rA) << 5) + (c & 31);
        g_bufB[idx]      = make_float2(ar, ai);
        g_bufB[idx + 32] = make_float2(0.5f * di, -0.5f * dr);
    }
}

/* 4 columns per block (one 4-col slice of a 32-wide tile); aligned blocked
   stage-in; epilogue: pu write, magnitude max, fused grad-y stats. */
__global__ void __launch_bounds__(256, 3) col_fft_kernel() {
    __shared__ float SMR[4][COL_SM], SMI[4][COL_SM];
    __shared__ float sred[8], sgy[8], sgy2[8];
    int tid = threadIdx.x;
    int b = blockIdx.x / 129;
    int g = blockIdx.x % 129;
    int c0 = 4 * g;
    int ct = c0 >> 5, cw0 = c0 & 31;
    const float2* src = g_bufB + ((size_t)b * CT + ct) * 1024 * 32 + cw0;
    /* stage-in: 32B-aligned 32B segments, conflict-free smem stores */
#pragma unroll
    for (int it = 0; it < 16; ++it) {
        int e = it * 256 + tid;
        int r = e >> 2, u = e & 3;
        float2 v = src[(size_t)r * 32 + u];
        SMR[u][PADI(r)] = v.x;
        SMI[u][PADI(r)] = v.y;
    }
    __syncthreads();
    int f = tid >> 6;
    int t = tid & 63;
    int cf = c0 + f;
    int active = (cf < WR);
    float* SR = SMR[f]; float* SI = SMI[f];

    /* stage0 (input from smem) */
    float vr[16], vi[16];
#pragma unroll
    for (int m = 0; m < 16; ++m) {
        int e = PADI(t + 64 * m);
        vr[m] = SR[e]; vi[m] = SI[e];
    }
    __syncthreads();
    dft16(vr, vi);
#pragma unroll
    for (int k = 0; k < 16; ++k) {
        int e = PADI(16 * t + k);
        SR[e] = vr[k]; SI[e] = vi[k];
    }
    __syncthreads();
    /* stage1 */
#pragma unroll
    for (int m = 0; m < 16; ++m) {
        int e = PADI(t + 64 * m);
        vr[m] = SR[e]; vi[m] = SI[e];
    }
    int jm = t & 15;
#pragma unroll
    for (int m = 1; m < 16; ++m) {
        float2 w = g_tw[4 * m * jm];
        float r = vr[m] * w.x - vi[m] * w.y;
        vi[m] = vr[m] * w.y + vi[m] * w.x;
        vr[m] = r;
    }
    dft16(vr, vi);
    __syncthreads();
    int base1 = (t >> 4) * 256 + jm;
#pragma unroll
    for (int k = 0; k < 16; ++k) {
        int e = PADI(base1 + 16 * k);
        SR[e] = vr[k]; SI[e] = vi[k];
    }
    __syncthreads();

    /* stage2 + epilogue; phase overwrites SR in place (thread-private slots) */
    float* pu = (float*)g_bufA;
    size_t outb = (size_t)(b * WR + (active ? cf : 0)) * H;
    float maxm2 = 0.0f;
    float phv[16];
#pragma unroll
    for (int u = 0; u < 4; ++u) {
        int j = t + 64 * u;
        float yr[4], yi[4];
        fft_stage2(SR, SI, j, yr, yi);
#pragma unroll
        for (int k = 0; k < 4; ++k) {
            float m2 = fmaf(yr[k], yr[k], yi[k] * yi[k]);
            maxm2 = fmaxf(maxm2, m2);
            float ph = fast_phase(yi[k], yr[k]);
            phv[u + 4 * k] = ph;
            SR[PADI(j + 256 * k)] = ph;
            if (active) pu[outb + j + 256 * k] = ph;
        }
    }
    __syncthreads();

    /* grad-y stats from smem phase column */
    float sy = 0.0f, sy2 = 0.0f;
    if (active) {
#pragma unroll
        for (int s = 0; s < 16; ++s) {
            int r = t + 64 * s;
            float pc = phv[s];
            float gy;
            if (r == 0)          gy = SR[PADI(1)] - pc;
            else if (r == 1023)  gy = pc - SR[PADI(1022)];
            else                 gy = 0.5f * (SR[PADI(r + 1)] - SR[PADI(r - 1)]);
            sy += gy;
            sy2 = fmaf(gy, gy, sy2);
        }
    } else {
        maxm2 = 0.0f;
    }
#pragma unroll
    for (int o = 16; o; o >>= 1) {
        maxm2 = fmaxf(maxm2, __shfl_xor_sync(0xffffffffu, maxm2, o));
        sy  += __shfl_xor_sync(0xffffffffu, sy,  o);
        sy2 += __shfl_xor_sync(0xffffffffu, sy2, o);
    }
    int w = tid >> 5;
    if ((tid & 31) == 0) { sred[w] = maxm2; sgy[w] = sy; sgy2[w] = sy2; }
    __syncthreads();
    if (t == 0 && active) {
        float mm = fmaxf(sred[2 * f], sred[2 * f + 1]);
        atomicMax(&g_magmax[b], __float_as_int(sqrtf(mm)));
        atomicAdd(&g_stats[b * 4 + 1], (double)(sgy[2 * f] + sgy[2 * f + 1]));
        atomicAdd(&g_stats[b * 4 + 3], (double)(sgy2[2 * f] + sgy2[2 * f + 1]));
    }
}

/* grad-x only stats (gy fused into col_fft) */
__global__ void __launch_bounds__(256) statsx_kernel() {
    int b = blockIdx.y;
    const float4* pu4 = (const float4*)((const float*)g_bufA + (size_t)b * NPIX);
    float sx = 0.0f, sx2 = 0.0f;
    const int NQ = NPIX / 4;
    for (int q = blockIdx.x * 256 + threadIdx.x; q < NQ; q += gridDim.x * 256) {
        int c = q >> 8;
        float4 up, dn; float fac;
        if (c == 0)          { dn = pu4[q + 256]; up = pu4[q];       fac = 1.0f; }
        else if (c == WR - 1){ up = pu4[q - 256]; dn = pu4[q];       fac = 1.0f; }
        else                 { up = pu4[q - 256]; dn = pu4[q + 256]; fac = 0.5f; }
        float g0 = fac * (dn.x - up.x);
        float g1 = fac * (dn.y - up.y);
        float g2 = fac * (dn.z - up.z);
        float g3 = fac * (dn.w - up.w);
        sx += g0 + g1 + g2 + g3;
        sx2 = fmaf(g0, g0, fmaf(g1, g1, fmaf(g2, g2, fmaf(g3, g3, sx2))));
    }
    __shared__ double sbuf[8];
    double v2[2] = {(double)sx, (double)sx2};
#pragma unroll
    for (int qq = 0; qq < 2; ++qq) {
        double tt = v2[qq];
#pragma unroll
        for (int o = 16; o; o >>= 1) tt += __shfl_down_sync(0xffffffffu, tt, o);
        if ((threadIdx.x & 31) == 0) sbuf[threadIdx.x >> 5] = tt;
        __syncthreads();
        if (threadIdx.x < 8) {
            tt = sbuf[threadIdx.x];
#pragma unroll
            for (int o = 4; o; o >>= 1) tt += __shfl_down_sync(0xffu, tt, o);
            if (threadIdx.x == 0) atomicAdd(&g_stats[b * 4 + 2 * qq], tt);
        }
        __syncthreads();
    }
}

/* coeffs GEMM with y-reflection symmetry: K halved (see R14). */
#define KC 128
#define KHALF (WR * 512)
__global__ void __launch_bounds__(128) gemm_kernel() {
    __shared__ float pm_s[64][KC + 4];
    __shared__ float z_s[64][KC + 4];
    const float* pu = (const float*)g_bufA;
    int tid = threadIdx.x;
    int bg = tid >> 3;
    int tg = tid & 7;
    int b0 = 2 * bg;
    float acc[8][2];
#pragma unroll
    for (int jj = 0; jj < 8; ++jj) { acc[jj][0] = 0.0f; acc[jj][1] = 0.0f; }

    for (int k0 = blockIdx.x * KC; k0 < KHALF; k0 += gridDim.x * KC) {
        int c  = k0 >> 9;
        int r0 = k0 & 511;
        int rh = r0 + tid;
        __syncthreads();
#pragma unroll 4
        for (int row = 0; row < 32; ++row) {
            const float* base = pu + ((size_t)row * WR + c) * 1024;
            float fv = base[rh];
            float mv = base[1023 - rh];
            pm_s[row][tid]      = fv + mv;
            pm_s[row + 32][tid] = fv - mv;
        }
        {
            float xg = (float)c * (1.0f / 256.0f) - 1.0f;
            float yg = (float)rh * (2.0f / 1023.0f) - 1.0f;
            float rr = xg * xg + yg * yg;
            float rho = sqrtf(rr);
            float mk = (rho <= 1.0f) ? 1.0f : 0.0f;
            float inv = 1.0f / rho;
            float c1 = xg * inv, s1 = yg * inv;
            float q1 = rho, q2 = q1 * q1;
            float q3 = q2 * q1, q4 = q2 * q2, q5 = q3 * q2, q6 = q3 * q3;
            float q7 = q4 * q3, q8 = q4 * q4, q9 = q5 * q4;
            float c2 = c1 * c1 - s1 * s1, s2 = 2.0f * s1 * c1;
            float c3 = c1 * c2 - s1 * s2, s3 = s1 * c2 + c1 * s2;
            float c4 = c1 * c3 - s1 * s3, s4 = s1 * c3 + c1 * s3;
            float c5 = c1 * c4 - s1 * s4, s5 = s1 * c4 + c1 * s4;
            float c6 = c1 * c5 - s1 * s5, s6 = s1 * c5 + c1 * s5;
            float c7 = c1 * c6 - s1 * s6, s7 = s1 * c6 + c1 * s6;
            float c8 = c1 * c7 - s1 * s7, s8 = s1 * c7 + c1 * s7;
            float c9 = c1 * c8 - s1 * s8, s9 = s1 * c8 + c1 * s8;
            float R31 = 3.0f * q3 - 2.0f * q1;
            float R42 = 4.0f * q4 - 3.0f * q2;
            float R53 = 5.0f * q5 - 4.0f * q3;
            float R51 = 10.0f * q5 - 12.0f * q3 + 3.0f * q1;
            float R64 = 6.0f * q6 - 5.0f * q4;
            float R62 = 15.0f * q6 - 20.0f * q4 + 6.0f * q2;
            float R75 = 7.0f * q7 - 6.0f * q5;
            float R73 = 21.0f * q7 - 30.0f * q5 + 10.0f * q3;
            float R71 = 35.0f * q7 - 60.0f * q5 + 30.0f * q3 - 4.0f * q1;
            float R86 = 8.0f * q8 - 7.0f * q6;
            float R84 = 28.0f * q8 - 42.0f * q6 + 15.0f * q4;
            float R82 = 56.0f * q8 - 105.0f * q6 + 60.0f * q4 - 10.0f * q2;
            float R97 = 9.0f * q9 - 8.0f * q7;
            float R95 = 36.0f * q9 - 56.0f * q7 + 21.0f * q5;
            float R93 = 84.0f * q9 - 168.0f * q7 + 105.0f * q5 - 20.0f * q3;
            float R91 = 126.0f * q9 - 280.0f * q7 + 210.0f * q5 - 60.0f * q3 + 5.0f * q1;
#define ZROW(rw, val) z_s[rw][tid] = (val) * mk
            ZROW(0, 1.0f);
            ZROW(1, q1 * c1);
            ZROW(2, 2.0f * q2 - 1.0f);
            ZROW(3, q2 * c2);
            ZROW(4, R31 * c1);
            ZROW(5, q3 * c3);
            ZROW(6, 6.0f * q4 - 6.0f * q2 + 1.0f);
            ZROW(7, R42 * c2);
            ZROW(8, q4 * c4);
            ZROW(9, R51 * c1);
            ZROW(10, R53 * c3);
            ZROW(11, q5 * c5);
            ZROW(12, 20.0f * q6 - 30.0f * q4 + 12.0f * q2 - 1.0f);
            ZROW(13, R62 * c2);
            ZROW(14, R64 * c4);
            ZROW(15, q6 * c6);
            ZROW(16, R71 * c1);
            ZROW(17, R73 * c3);
            ZROW(18, R75 * c5);
            ZROW(19, q7 * c7);
            ZROW(20, 70.0f * q8 - 140.0f * q6 + 90.0f * q4 - 20.0f * q2 + 1.0f);
            ZROW(21, R82 * c2);
            ZROW(22, R84 * c4);
            ZROW(23, R86 * c6);
            ZROW(24, q8 * c8);
            ZROW(25, R91 * c1);
            ZROW(26, R93 * c3);
            ZROW(27, R95 * c5);
            ZROW(28, R97 * c7);
            ZROW(29, q9 * c9);
            z_s[30][tid] = 0.0f;
            z_s[31][tid] = 0.0f;
            ZROW(32, q1 * s1);
            ZROW(33, q2 * s2);
            ZROW(34, q3 * s3);
            ZROW(35, R31 * s1);
            ZROW(36, q4 * s4);
            ZROW(37, R42 * s2);
            ZROW(38, q5 * s5);
            ZROW(39, R53 * s3);
            ZROW(40, R51 * s1);
            ZROW(41, q6 * s6);
            ZROW(42, R64 * s4);
            ZROW(43, R62 * s2);
            ZROW(44, q7 * s7);
            ZROW(45, R75 * s5);
            ZROW(46, R73 * s3);
            ZROW(47, R71 * s1);
            ZROW(48, q8 * s8);
            ZROW(49, R86 * s6);
            ZROW(50, R84 * s4);
            ZROW(51, R82 * s2);
            ZROW(52, q9 * s9);
            ZROW(53, R97 * s7);
            ZROW(54, R95 * s5);
            ZROW(55, R93 * s3);
            ZROW(56, R91 * s1);
#pragma unroll
            for (int rw = 57; rw < 64; ++rw) z_s[rw][tid] = 0.0f;
#undef ZROW
            unsigned bal = __ballot_sync(0xffffffffu, mk > 0.5f);
            if ((tid & 31) == 0) atomicAdd(&g_maskcnt, 2 * __popc(bal));
        }
        __syncthreads();
#pragma unroll 4
        for (int kk = 0; kk < KC; kk += 4) {
            float4 ps0 = *(const float4*)&pm_s[b0][kk];
            float4 ps1 = *(const float4*)&pm_s[b0 + 1][kk];
            float4 pd0 = *(const float4*)&pm_s[b0 + 32][kk];
            float4 pd1 = *(const float4*)&pm_s[b0 + 33][kk];
#pragma unroll
            for (int jj = 0; jj < 4; ++jj) {
                float4 zz = *(const float4*)&z_s[8 * jj + tg][kk];
                acc[jj][0] = fmaf(ps0.x, zz.x, fmaf(ps0.y, zz.y, fmaf(ps0.z, zz.z, fmaf(ps0.w, zz.w, acc[jj][0]))));
                acc[jj][1] = fmaf(ps1.x, zz.x, fmaf(ps1.y, zz.y, fmaf(ps1.z, zz.z, fmaf(ps1.w, zz.w, acc[jj][1]))));
            }
#pragma unroll
            for (int jj = 4; jj < 8; ++jj) {
                float4 zz = *(const float4*)&z_s[8 * jj + tg][kk];
                acc[jj][0] = fmaf(pd0.x, zz.x, fmaf(pd0.y, zz.y, fmaf(pd0.z, zz.z, fmaf(pd0.w, zz.w, acc[jj][0]))));
                acc[jj][1] = fmaf(pd1.x, zz.x, fmaf(pd1.y, zz.y, fmaf(pd1.z, zz.z, fmaf(pd1.w, zz.w, acc[jj][1]))));
            }
        }
    }
#pragma unroll
    for (int jj = 0; jj < 8; ++jj) {
        int rw = 8 * jj + tg;
        int tm = ROW2TERM[rw];
        if (tm != 255) {
            atomicAdd(&g_coeff[b0 * TP + tm], acc[jj][0]);
            atomicAdd(&g_coeff[(b0 + 1) * TP + tm], acc[jj][1]);
        }
    }
}

__global__ void finalize_kernel(float* __restrict__ out) {
    int b = blockIdx.x;
    int j = threadIdx.x;
    if (j < 55) {
        out[b * 60 + j] = g_coeff[b * TP + j] / (float)g_maskcnt;
    } else if (j < 60) {
        double N = (double)NPIX;
        double sx = g_stats[b * 4 + 0], sy = g_stats[b * 4 + 1];
        double sx2 = g_stats[b * 4 + 2], sy2 = g_stats[b * 4 + 3];
        float v;
        if (j == 55)      v = (float)(sx / N);
        else if (j == 56) v = (float)(sy / N);
        else if (j == 57) v = (float)sqrt(fmax(0.0, (sx2 - sx * sx / N) / (N - 1.0)));
        else if (j == 58) v = (float)sqrt(fmax(0.0, (sy2 - sy * sy / N) / (N - 1.0)));
        else              v = __int_as_float(g_magmax[b]);
        out[b * 60 + j] = v;
    }
}

extern "C" void kernel_launch(void* const* d_in, const int* in_sizes, int n_in,
                              void* d_out, int out_size) {
    (void)in_sizes; (void)n_in; (void)out_size;
    const float* x = (const float*)d_in[0];
    float* out = (float*)d_out;

    init_kernel<<<1, 1024>>>();
    row_fft_kernel<<<BATCH * H / 4, 128>>>(x);
    col_fft_kernel<<<BATCH * 129, 256>>>();
    statsx_kernel<<<dim3(64, BATCH), 256>>>();
    gemm_kernel<<<684, 128>>>();
    finalize_kernel<<<BATCH, 64>>>(out);
}

// round 17
// speedup vs baseline: 1.5706x; 1.0142x over previous
#include <cuda_runtime.h>
#include <math.h>

#define BATCH 32
#define H 1024
#define W 1024
#define WR 513
#define NPIX (WR * H)
#define TP 56
#define TWO_PI 6.28318530717958647692f

#define PADI(e) ((e) + 5 * ((e) >> 5))
#define FFT_SM 1184
#define COL_SM 1192
#define CT 17   /* column tiles of 32 */

__device__ float2 g_bufA[(size_t)BATCH * H * WR];            /* pu [b][c][r] floats */
__device__ float2 g_bufB[(size_t)BATCH * CT * 1024 * 32];    /* spectra, blocked [b][ct][r][cw] */
__device__ float2 g_tw[1024];
__device__ float  g_coeff[BATCH * TP];
__device__ double g_stats[BATCH * 4];   /* sgx, sgy, sgx2, sgy2 */
__device__ int    g_magmax[BATCH];
__device__ int    g_maskcnt;

/* z_s row -> original term index (255 = pad) */
__device__ const unsigned char ROW2TERM[64] = {
    0,2,4,5,8,9,12,13,14,18,19,20,24,25,26,27,
    32,33,34,35,40,41,42,43,44,50,51,52,53,54,255,255,
    1,3,6,7,10,11,15,16,17,21,22,23,28,29,30,31,
    36,37,38,39,45,46,47,48,49,255,255,255,255,255,255,255
};

__global__ void init_kernel() {
    int t = threadIdx.x;   /* 1024 threads */
    float s, c;
    sincospif(-(float)t / 512.0f, &s, &c);
    g_tw[t] = make_float2(c, s);
    for (int i = t; i < BATCH * TP; i += 1024) g_coeff[i] = 0.0f;
    if (t < BATCH * 4) g_stats[t] = 0.0;
    if (t < BATCH)     g_magmax[t] = 0;
    if (t == 0)        g_maskcnt = 0;
}

/* atan2 -> [0, 2pi) unwrapped phase; minimax poly, max abs err ~1e-8 */
__device__ __forceinline__ float fast_phase(float y, float x) {
    float ax = fabsf(x), ay = fabsf(y);
    float mn = fminf(ax, ay), mx = fmaxf(ax, ay);
    float r = (mx == 0.0f) ? 0.0f : __fdividef(mn, mx);
    float a = r * r;
    float p = fmaf(a, -0.0040540580f, 0.0218612288f);
    p = fmaf(a, p, -0.0559098861f);
    p = fmaf(a, p, 0.0964200441f);
    p = fmaf(a, p, -0.1390853351f);
    p = fmaf(a, p, 0.1994653599f);
    p = fmaf(a, p, -0.3332985605f);
    p = fmaf(a, p, 0.9999993329f);
    float th = r * p;
    if (ay > ax)    th = 1.57079632679489662f - th;
    if (x < 0.0f)   th = 3.14159265358979324f - th;
    if (y < 0.0f)   th = TWO_PI - th;
    return th;
}

/* DFT-16 fully in registers. */
__device__ __forceinline__ void dft16(float* vr, float* vi) {
    const float C1 = 0.92387953251128675613f;
    const float S1 = 0.38268343236508977173f;
    const float C2 = 0.70710678118654752440f;
    float tr[4][4], ti[4][4];
#pragma unroll
    for (int a = 0; a < 4; ++a) {
        float x0r = vr[a],      x0i = vi[a];
        float x1r = vr[a + 4],  x1i = vi[a + 4];
        float x2r = vr[a + 8],  x2i = vi[a + 8];
        float x3r = vr[a + 12], x3i = vi[a + 12];
        float s0r = x0r + x2r, s0i = x0i + x2i;
        float d0r = x0r - x2r, d0i = x0i - x2i;
        float s1r = x1r + x3r, s1i = x1i + x3i;
        float d1r = x1r - x3r, d1i = x1i - x3i;
        tr[a][0] = s0r + s1r; ti[a][0] = s0i + s1i;
        tr[a][1] = d0r + d1i; ti[a][1] = d0i - d1r;
        tr[a][2] = s0r - s1r; ti[a][2] = s0i - s1i;
        tr[a][3] = d0r - d1i; ti[a][3] = d0i + d1r;
    }
#pragma unroll
    for (int a = 1; a < 4; ++a) {
#pragma unroll
        for (int c = 1; c < 4; ++c) {
            int k = a * c;
            float wr, wi;
            if (k == 1)      { wr =  C1; wi = -S1; }
            else if (k == 2) { wr =  C2; wi = -C2; }
            else if (k == 3) { wr =  S1; wi = -C1; }
            else if (k == 4) { wr = 0.f; wi = -1.f; }
            else if (k == 6) { wr = -C2; wi = -C2; }
            else             { wr = -C1; wi =  S1; }
            float r = tr[a][c] * wr - ti[a][c] * wi;
            ti[a][c] = tr[a][c] * wi + ti[a][c] * wr;
            tr[a][c] = r;
        }
    }
#pragma unroll
    for (int c = 0; c < 4; ++c) {
        float s0r = tr[0][c] + tr[2][c], s0i = ti[0][c] + ti[2][c];
        float d0r = tr[0][c] - tr[2][c], d0i = ti[0][c] - ti[2][c];
        float s1r = tr[1][c] + tr[3][c], s1i = ti[1][c] + ti[3][c];
        float d1r = tr[1][c] - tr[3][c], d1i = ti[1][c] - ti[3][c];
        vr[c]      = s0r + s1r; vi[c]      = s0i + s1i;
        vr[c + 4]  = d0r + d1i; vi[c + 4]  = d0i - d1r;
        vr[c + 8]  = s0r - s1r; vi[c + 8]  = s0i - s1i;
        vr[c + 12] = d0r - d1i; vi[c + 12] = d0i + d1r;
    }
}

__device__ __forceinline__ void fft_stages01(float* vr, float* vi,
                                             float* SR, float* SI, int t) {
    dft16(vr, vi);
#pragma unroll
    for (int k = 0; k < 16; ++k) {
        int e = PADI(16 * t + k);
        SR[e] = vr[k]; SI[e] = vi[k];
    }
    __syncthreads();
#pragma unroll
    for (int m = 0; m < 16; ++m) {
        int e = PADI(t + 64 * m);
        vr[m] = SR[e]; vi[m] = SI[e];
    }
    int jm = t & 15;
#pragma unroll
    for (int m = 1; m < 16; ++m) {
        float2 w = g_tw[4 * m * jm];
        float r = vr[m] * w.x - vi[m] * w.y;
        vi[m] = vr[m] * w.y + vi[m] * w.x;
        vr[m] = r;
    }
    dft16(vr, vi);
    __syncthreads();
    int base1 = (t >> 4) * 256 + jm;
#pragma unroll
    for (int k = 0; k < 16; ++k) {
        int e = PADI(base1 + 16 * k);
        SR[e] = vr[k]; SI[e] = vi[k];
    }
    __syncthreads();
}

__device__ __forceinline__ void fft_stage2(const float* SR, const float* SI,
                                           int j, float* yr, float* yi) {
    float ar[4], ai[4];
#pragma unroll
    for (int m = 0; m < 4; ++m) {
        int e = PADI(j + 256 * m);
        ar[m] = SR[e]; ai[m] = SI[e];
    }
#pragma unroll
    for (int m = 1; m < 4; ++m) {
        float2 w = g_tw[m * j];
        float r = ar[m] * w.x - ai[m] * w.y;
        ai[m] = ar[m] * w.y + ai[m] * w.x;
        ar[m] = r;
    }
    float s0r = ar[0] + ar[2], s0i = ai[0] + ai[2];
    float d0r = ar[0] - ar[2], d0i = ai[0] - ai[2];
    float s1r = ar[1] + ar[3], s1i = ai[1] + ai[3];
    float d1r = ar[1] - ar[3], d1i = ai[1] - ai[3];
    yr[0] = s0r + s1r; yi[0] = s0i + s1i;
    yr[1] = d0r + d1i; yi[1] = d0i - d1r;
    yr[2] = s0r - s1r; yi[2] = s0i - s1i;
    yr[3] = d0r - d1i; yi[3] = d0i + d1r;
}

/* Two real rows packed per FFT; 2 FFTs per block.
   Output written to blocked layout [b][ct][r][cw] (256B/warp segments). */
__global__ void __launch_bounds__(128) row_fft_kernel(const float* __restrict__ x) {
    __shared__ float smr[2][FFT_SM], smi[2][FFT_SM];
    int f = threadIdx.x >> 6;
    int t = threadIdx.x & 63;
    int pr = blockIdx.x * 2 + f;
    float* SR = smr[f]; float* SI = smi[f];
    const float* rowA = x + (size_t)(2 * pr) * W;
    const float* rowB = rowA + W;
    float vr[16], vi[16];
#pragma unroll
    for (int m = 0; m < 16; ++m) {
        int idx = t + 64 * m;
        vr[m] = rowA[idx]; vi[m] = rowB[idx];
    }
    fft_stages01(vr, vi, SR, SI, t);
#pragma unroll
    for (int u = 0; u < 4; ++u) {
        int j = t + 64 * u;
        float yr[4], yi[4];
        fft_stage2(SR, SI, j, yr, yi);
#pragma unroll
        for (int k = 0; k < 4; ++k) {
            int e = PADI(j + 256 * k);
            SR[e] = yr[k]; SI[e] = yi[k];
        }
    }
    __syncthreads();
    int rowidx = 2 * pr;
    int b  = rowidx >> 10;
    int rA = rowidx & 1023;
    for (int c = t; c < WR; c += 64) {
        int cn = (1024 - c) & 1023;
        float Zcr = SR[PADI(c)],  Zci = SI[PADI(c)];
        float Znr = SR[PADI(cn)], Zni = SI[PADI(cn)];
        float ar = 0.5f * (Zcr + Znr);
        float ai = 0.5f * (Zci - Zni);
        float dr = Zcr - Znr;
        float di = Zci + Zni;
        size_t idx = ((((size_t)b * CT + (c >> 5)) * 1024 + rA) << 5) + (c & 31);
        g_bufB[idx]      = make_float2(ar, ai);
        g_bufB[idx + 32] = make_float2(0.5f * di, -0.5f * dr);
    }
}

/* 4 columns per block; float4 aligned blocked stage-in;
   epilogue: pu write, magnitude max, fused grad-y stats. */
__global__ void __launch_bounds__(256, 3) col_fft_kernel() {
    __shared__ float SMR[4][COL_SM], SMI[4][COL_SM];
    __shared__ float sred[8], sgy[8], sgy2[8];
    int tid = threadIdx.x;
    int b = blockIdx.x / 129;
    int g = blockIdx.x % 129;
    int c0 = 4 * g;
    int ct = c0 >> 5, cw0 = c0 & 31;
    const float2* src = g_bufB + ((size_t)b * CT + ct) * 1024 * 32 + cw0;
    /* stage-in: float4 = two adjacent cw (16B aligned since cw0 % 4 == 0) */
#pragma unroll
    for (int it = 0; it < 8; ++it) {
        int p = it * 256 + tid;        /* 0..2047 */
        int r = p >> 1, u2 = (p & 1) * 2;
        float4 v = *(const float4*)(src + (size_t)r * 32 + u2);
        int e = PADI(r);
        SMR[u2][e]     = v.x; SMI[u2][e]     = v.y;
        SMR[u2 + 1][e] = v.z; SMI[u2 + 1][e] = v.w;
    }
    __syncthreads();
    int f = tid >> 6;
    int t = tid & 63;
    int cf = c0 + f;
    int active = (cf < WR);
    float* SR = SMR[f]; float* SI = SMI[f];

    /* stage0 (input from smem) */
    float vr[16], vi[16];
#pragma unroll
    for (int m = 0; m < 16; ++m) {
        int e = PADI(t + 64 * m);
        vr[m] = SR[e]; vi[m] = SI[e];
    }
    __syncthreads();
    dft16(vr, vi);
#pragma unroll
    for (int k = 0; k < 16; ++k) {
        int e = PADI(16 * t + k);
        SR[e] = vr[k]; SI[e] = vi[k];
    }
    __syncthreads();
    /* stage1 */
#pragma unroll
    for (int m = 0; m < 16; ++m) {
        int e = PADI(t + 64 * m);
        vr[m] = SR[e]; vi[m] = SI[e];
    }
    int jm = t & 15;
#pragma unroll
    for (int m = 1; m < 16; ++m) {
        float2 w = g_tw[4 * m * jm];
        float r = vr[m] * w.x - vi[m] * w.y;
        vi[m] = vr[m] * w.y + vi[m] * w.x;
        vr[m] = r;
    }
    dft16(vr, vi);
    __syncthreads();
    int base1 = (t >> 4) * 256 + jm;
#pragma unroll
    for (int k = 0; k < 16; ++k) {
        int e = PADI(base1 + 16 * k);
        SR[e] = vr[k]; SI[e] = vi[k];
    }
    __syncthreads();

    /* stage2 + epilogue; phase overwrites SR in place (thread-private slots) */
    float* pu = (float*)g_bufA;
    size_t outb = (size_t)(b * WR + (active ? cf : 0)) * H;
    float maxm2 = 0.0f;
    float phv[16];
#pragma unroll
    for (int u = 0; u < 4; ++u) {
        int j = t + 64 * u;
        float yr[4], yi[4];
        fft_stage2(SR, SI, j, yr, yi);
#pragma unroll
        for (int k = 0; k < 4; ++k) {
            float m2 = fmaf(yr[k], yr[k], yi[k] * yi[k]);
            maxm2 = fmaxf(maxm2, m2);
            float ph = fast_phase(yi[k], yr[k]);
            phv[u + 4 * k] = ph;
            SR[PADI(j + 256 * k)] = ph;
            if (active) pu[outb + j + 256 * k] = ph;
        }
    }
    __syncthreads();

    /* grad-y stats from smem phase column */
    float sy = 0.0f, sy2 = 0.0f;
    if (active) {
#pragma unroll
        for (int s = 0; s < 16; ++s) {
            int r = t + 64 * s;
            float pc = phv[s];
            float gy;
            if (r == 0)          gy = SR[PADI(1)] - pc;
            else if (r == 1023)  gy = pc - SR[PADI(1022)];
            else                 gy = 0.5f * (SR[PADI(r + 1)] - SR[PADI(r - 1)]);
            sy += gy;
            sy2 = fmaf(gy, gy, sy2);
        }
    } else {
        maxm2 = 0.0f;
    }
#pragma unroll
    for (int o = 16; o; o >>= 1) {
        maxm2 = fmaxf(maxm2, __shfl_xor_sync(0xffffffffu, maxm2, o));
        sy  += __shfl_xor_sync(0xffffffffu, sy,  o);
        sy2 += __shfl_xor_sync(0xffffffffu, sy2, o);
    }
    int w = tid >> 5;
    if ((tid & 31) == 0) { sred[w] = maxm2; sgy[w] = sy; sgy2[w] = sy2; }
    __syncthreads();
    if (t == 0 && active) {
        float mm = fmaxf(sred[2 * f], sred[2 * f + 1]);
        atomicMax(&g_magmax[b], __float_as_int(sqrtf(mm)));
        atomicAdd(&g_stats[b * 4 + 1], (double)(sgy[2 * f] + sgy[2 * f + 1]));
        atomicAdd(&g_stats[b * 4 + 3], (double)(sgy2[2 * f] + sgy2[2 * f + 1]));
    }
}

/* grad-x stats: column-marching stencil, 1 load per column step.
   Stripe s covers columns [16s, 16s+16) (last stripe +1); thread owns r-quad. */
__global__ void __launch_bounds__(256) statsx_kernel() {
    int b = blockIdx.y;
    int s = blockIdx.x;                 /* 0..31 */
    const float4* pu4 = (const float4*)((const float*)g_bufA + (size_t)b * NPIX);
    int tid = threadIdx.x;              /* r-quad 0..255 */
    int c0 = s * 16;
    int c1 = (s == 31) ? WR : c0 + 16;
    float sx = 0.0f, sx2 = 0.0f;
    float4 cur  = pu4[(size_t)c0 * 256 + tid];
    float4 prev = (c0 == 0) ? cur : pu4[(size_t)(c0 - 1) * 256 + tid];
#pragma unroll 4
    for (int c = c0; c < c1; ++c) {
        float4 next = (c == WR - 1) ? cur : pu4[(size_t)(c + 1) * 256 + tid];
        float fac = (c == 0 || c == WR - 1) ? 1.0f : 0.5f;
        float g0 = fac * (next.x - prev.x);
        float g1 = fac * (next.y - prev.y);
        float g2 = fac * (next.z - prev.z);
        float g3 = fac * (next.w - prev.w);
        sx += g0 + g1 + g2 + g3;
        sx2 = fmaf(g0, g0, fmaf(g1, g1, fmaf(g2, g2, fmaf(g3, g3, sx2))));
        prev = cur; cur = next;
    }
    __shared__ double sbuf[8];
    double v2[2] = {(double)sx, (double)sx2};
#pragma unroll
    for (int qq = 0; qq < 2; ++qq) {
        double tt = v2[qq];
#pragma unroll
        for (int o = 16; o; o >>= 1) tt += __shfl_down_sync(0xffffffffu, tt, o);
        if ((tid & 31) == 0) sbuf[tid >> 5] = tt;
        __syncthreads();
        if (tid < 8) {
            tt = sbuf[tid];
#pragma unroll
            for (int o = 4; o; o >>= 1) tt += __shfl_down_sync(0xffu, tt, o);
            if (tid == 0) atomicAdd(&g_stats[b * 4 + 2 * qq], tt);
        }
        __syncthreads();
    }
}

/* coeffs GEMM with y-reflection symmetry: K halved (see R14). */
#define KC 128
#define KHALF (WR * 512)
__global__ void __launch_bounds__(128) gemm_kernel() {
    __shared__ float pm_s[64][KC + 4];
    __shared__ float z_s[64][KC + 4];
    const float* pu = (const float*)g_bufA;
    int tid = threadIdx.x;
    int bg = tid >> 3;
    int tg = tid & 7;
    int b0 = 2 * bg;
    float acc[8][2];
#pragma unroll
    for (int jj = 0; jj < 8; ++jj) { acc[jj][0] = 0.0f; acc[jj][1] = 0.0f; }

    for (int k0 = blockIdx.x * KC; k0 < KHALF; k0 += gridDim.x * KC) {
        int c  = k0 >> 9;
        int r0 = k0 & 511;
        int rh = r0 + tid;
        __syncthreads();
#pragma unroll 4
        for (int row = 0; row < 32; ++row) {
            const float* base = pu + ((size_t)row * WR + c) * 1024;
            float fv = base[rh];
            float mv = base[1023 - rh];
            pm_s[row][tid]      = fv + mv;
            pm_s[row + 32][tid] = fv - mv;
        }
        {
            float xg = (float)c * (1.0f / 256.0f) - 1.0f;
            float yg = (float)rh * (2.0f / 1023.0f) - 1.0f;
            float rr = xg * xg + yg * yg;
            float rho = sqrtf(rr);
            float mk = (rho <= 1.0f) ? 1.0f : 0.0f;
            float inv = 1.0f / rho;
            float c1 = xg * inv, s1 = yg * inv;
            float q1 = rho, q2 = q1 * q1;
            float q3 = q2 * q1, q4 = q2 * q2, q5 = q3 * q2, q6 = q3 * q3;
            float q7 = q4 * q3, q8 = q4 * q4, q9 = q5 * q4;
            float c2 = c1 * c1 - s1 * s1, s2 = 2.0f * s1 * c1;
            float c3 = c1 * c2 - s1 * s2, s3 = s1 * c2 + c1 * s2;
            float c4 = c1 * c3 - s1 * s3, s4 = s1 * c3 + c1 * s3;
            float c5 = c1 * c4 - s1 * s4, s5 = s1 * c4 + c1 * s4;
            float c6 = c1 * c5 - s1 * s5, s6 = s1 * c5 + c1 * s5;
            float c7 = c1 * c6 - s1 * s6, s7 = s1 * c6 + c1 * s6;
            float c8 = c1 * c7 - s1 * s7, s8 = s1 * c7 + c1 * s7;
            float c9 = c1 * c8 - s1 * s8, s9 = s1 * c8 + c1 * s8;
            float R31 = 3.0f * q3 - 2.0f * q1;
            float R42 = 4.0f * q4 - 3.0f * q2;
            float R53 = 5.0f * q5 - 4.0f * q3;
            float R51 = 10.0f * q5 - 12.0f * q3 + 3.0f * q1;
            float R64 = 6.0f * q6 - 5.0f * q4;
            float R62 = 15.0f * q6 - 20.0f * q4 + 6.0f * q2;
            float R75 = 7.0f * q7 - 6.0f * q5;
            float R73 = 21.0f * q7 - 30.0f * q5 + 10.0f * q3;
            float R71 = 35.0f * q7 - 60.0f * q5 + 30.0f * q3 - 4.0f * q1;
            float R86 = 8.0f * q8 - 7.0f * q6;
            float R84 = 28.0f * q8 - 42.0f * q6 + 15.0f * q4;
            float R82 = 56.0f * q8 - 105.0f * q6 + 60.0f * q4 - 10.0f * q2;
            float R97 = 9.0f * q9 - 8.0f * q7;
            float R95 = 36.0f * q9 - 56.0f * q7 + 21.0f * q5;
            float R93 = 84.0f * q9 - 168.0f * q7 + 105.0f * q5 - 20.0f * q3;
            float R91 = 126.0f * q9 - 280.0f * q7 + 210.0f * q5 - 60.0f * q3 + 5.0f * q1;
#define ZROW(rw, val) z_s[rw][tid] = (val) * mk
            ZROW(0, 1.0f);
            ZROW(1, q1 * c1);
            ZROW(2, 2.0f * q2 - 1.0f);
            ZROW(3, q2 * c2);
            ZROW(4, R31 * c1);
            ZROW(5, q3 * c3);
            ZROW(6, 6.0f * q4 - 6.0f * q2 + 1.0f);
            ZROW(7, R42 * c2);
            ZROW(8, q4 * c4);
            ZROW(9, R51 * c1);
            ZROW(10, R53 * c3);
            ZROW(11, q5 * c5);
            ZROW(12, 20.0f * q6 - 30.0f * q4 + 12.0f * q2 - 1.0f);
            ZROW(13, R62 * c2);
            ZROW(14, R64 * c4);
            ZROW(15, q6 * c6);
            ZROW(16, R71 * c1);
            ZROW(17, R73 * c3);
            ZROW(18, R75 * c5);
            ZROW(19, q7 * c7);
            ZROW(20, 70.0f * q8 - 140.0f * q6 + 90.0f * q4 - 20.0f * q2 + 1.0f);
            ZROW(21, R82 * c2);
            ZROW(22, R84 * c4);
            ZROW(23, R86 * c6);
            ZROW(24, q8 * c8);
            ZROW(25, R91 * c1);
            ZROW(26, R93 * c3);
            ZROW(27, R95 * c5);
            ZROW(28, R97 * c7);
            ZROW(29, q9 * c9);
            z_s[30][tid] = 0.0f;
            z_s[31][tid] = 0.0f;
            ZROW(32, q1 * s1);
            ZROW(33, q2 * s2);
            ZROW(34, q3 * s3);
            ZROW(35, R31 * s1);
            ZROW(36, q4 * s4);
            ZROW(37, R42 * s2);
            ZROW(38, q5 * s5);
            ZROW(39, R53 * s3);
            ZROW(40, R51 * s1);
            ZROW(41, q6 * s6);
            ZROW(42, R64 * s4);
            ZROW(43, R62 * s2);
            ZROW(44, q7 * s7);
            ZROW(45, R75 * s5);
            ZROW(46, R73 * s3);
            ZROW(47, R71 * s1);
            ZROW(48, q8 * s8);
            ZROW(49, R86 * s6);
            ZROW(50, R84 * s4);
            ZROW(51, R82 * s2);
            ZROW(52, q9 * s9);
            ZROW(53, R97 * s7);
            ZROW(54, R95 * s5);
            ZROW(55, R93 * s3);
            ZROW(56, R91 * s1);
#pragma unroll
            for (int rw = 57; rw < 64; ++rw) z_s[rw][tid] = 0.0f;
#undef ZROW
            unsigned bal = __ballot_sync(0xffffffffu, mk > 0.5f);
            if ((tid & 31) == 0) atomicAdd(&g_maskcnt, 2 * __popc(bal));
        }
        __syncthreads();
#pragma unroll 4
        for (int kk = 0; kk < KC; kk += 4) {
            float4 ps0 = *(const float4*)&pm_s[b0][kk];
            float4 ps1 = *(const float4*)&pm_s[b0 + 1][kk];
            float4 pd0 = *(const float4*)&pm_s[b0 + 32][kk];
            float4 pd1 = *(const float4*)&pm_s[b0 + 33][kk];
#pragma unroll
            for (int jj = 0; jj < 4; ++jj) {
                float4 zz = *(const float4*)&z_s[8 * jj + tg][kk];
                acc[jj][0] = fmaf(ps0.x, zz.x, fmaf(ps0.y, zz.y, fmaf(ps0.z, zz.z, fmaf(ps0.w, zz.w, acc[jj][0]))));
                acc[jj][1] = fmaf(ps1.x, zz.x, fmaf(ps1.y, zz.y, fmaf(ps1.z, zz.z, fmaf(ps1.w, zz.w, acc[jj][1]))));
            }
#pragma unroll
            for (int jj = 4; jj < 8; ++jj) {
                float4 zz = *(const float4*)&z_s[8 * jj + tg][kk];
                acc[jj][0] = fmaf(pd0.x, zz.x, fmaf(pd0.y, zz.y, fmaf(pd0.z, zz.z, fmaf(pd0.w, zz.w, acc[jj][0]))));
                acc[jj][1] = fmaf(pd1.x, zz.x, fmaf(pd1.y, zz.y, fmaf(pd1.z, zz.z, fmaf(pd1.w, zz.w, acc[jj][1]))));
            }
        }
    }
#pragma unroll
    for (int jj = 0; jj < 8; ++jj) {
        int rw = 8 * jj + tg;
        int tm = ROW2TERM[rw];
        if (tm != 255) {
            atomicAdd(&g_coeff[b0 * TP + tm], acc[jj][0]);
            atomicAdd(&g_coeff[(b0 + 1) * TP + tm], acc[jj][1]);
        }
    }
}

__global__ void finalize_kernel(float* __restrict__ out) {
    int b = blockIdx.x;
    int j = threadIdx.x;
    if (j < 55) {
        out[b * 60 + j] = g_coeff[b * TP + j] / (float)g_maskcnt;
    } else if (j < 60) {
        double N = (double)NPIX;
        double sx = g_stats[b * 4 + 0], sy = g_stats[b * 4 + 1];
        double sx2 = g_stats[b * 4 + 2], sy2 = g_stats[b * 4 + 3];
        float v;
        if (j == 55)      v = (float)(sx / N);
        else if (j == 56) v = (float)(sy / N);
        else if (j == 57) v = (float)sqrt(fmax(0.0, (sx2 - sx * sx / N) / (N - 1.0)));
        else if (j == 58) v = (float)sqrt(fmax(0.0, (sy2 - sy * sy / N) / (N - 1.0)));
        else              v = __int_as_float(g_magmax[b]);
        out[b * 60 + j] = v;
    }
}

extern "C" void kernel_launch(void* const* d_in, const int* in_sizes, int n_in,
                              void* d_out, int out_size) {
    (void)in_sizes; (void)n_in; (void)out_size;
    const float* x = (const float*)d_in[0];
    float* out = (float*)d_out;

    init_kernel<<<1, 1024>>>();
    row_fft_kernel<<<BATCH * H / 4, 128>>>(x);
    col_fft_kernel<<<BATCH * 129, 256>>>();
    statsx_kernel<<<dim3(32, BATCH), 256>>>();
    gemm_kernel<<<684, 128>>>();
    finalize_kernel<<<BATCH, 64>>>(out);
}